// round 8
// baseline (speedup 1.0000x reference)
#include <cuda_runtime.h>
#include <cstdint>

typedef unsigned long long u64;

#define L_ 1024
#define B_ 2048
#define NE (L_ * B_)

// scratch: gate pre-activations in HMMA fragment-tile layout (see k1), plus
// final hidden state for the decoder tail.
__device__ float g_gates[(size_t)NE * 48];
__device__ float g_hlast[B_ * 16];

#define LOG2E 1.4426950408889634f

__device__ __forceinline__ float ex2f(float x) {
    float y; asm("ex2.approx.f32 %0, %1;" : "=f"(y) : "f"(x)); return y;
}
__device__ __forceinline__ float rcpf(float x) {
    float y; asm("rcp.approx.f32 %0, %1;" : "=f"(y) : "f"(x)); return y;
}
__device__ __forceinline__ float sigf(float x) {
    return rcpf(1.0f + ex2f(-LOG2E * x));
}
__device__ __forceinline__ float mytanh(float x) {
    return fmaf(2.0f, sigf(2.0f * x), -1.0f);
}

// ---- packed f32x2 helpers ----
__device__ __forceinline__ u64 pk2(float lo, float hi) {
    u64 r; asm("mov.b64 %0, {%1, %2};" : "=l"(r) : "f"(lo), "f"(hi)); return r;
}
__device__ __forceinline__ void upk2(float& lo, float& hi, u64 v) {
    asm("mov.b64 {%0, %1}, %2;" : "=f"(lo), "=f"(hi) : "l"(v));
}
__device__ __forceinline__ u64 ffma2(u64 a, u64 b, u64 c) {
    u64 d; asm("fma.rn.f32x2 %0, %1, %2, %3;" : "=l"(d) : "l"(a), "l"(b), "l"(c)); return d;
}
__device__ __forceinline__ u64 fadd2(u64 a, u64 b) {
    u64 d; asm("add.rn.f32x2 %0, %1, %2;" : "=l"(d) : "l"(a), "l"(b)); return d;
}
__device__ __forceinline__ unsigned cvt_tf32(float f) {
    unsigned r; asm("cvt.rna.tf32.f32 %0, %1;" : "=r"(r) : "f"(f)); return r;
}
__device__ __forceinline__ void mma_tf32(float* c, const unsigned* a, unsigned b0, unsigned b1) {
    asm volatile(
        "mma.sync.aligned.m16n8k8.row.col.f32.tf32.tf32.f32 "
        "{%0,%1,%2,%3}, {%4,%5,%6,%7}, {%8,%9}, {%0,%1,%2,%3};"
        : "+f"(c[0]), "+f"(c[1]), "+f"(c[2]), "+f"(c[3])
        : "r"(a[0]), "r"(a[1]), "r"(a[2]), "r"(a[3]), "r"(b0), "r"(b1));
}

// ============================================================================
// K1: preprocess MLPs (fp32) + gate GEMM on tensor cores; fragments stored
// directly in fragment-tile layout (coalesced STG.128). 4 CTAs/SM.
// ============================================================================
#define K1T 128
#define EMB_STRIDE 36

__global__ void __launch_bounds__(K1T, 4) k1_gates(
    const float* __restrict__ u_in, const float* __restrict__ x_in,
    const float* __restrict__ pu_W1, const float* __restrict__ pu_b1,
    const float* __restrict__ pu_W2, const float* __restrict__ pu_b2,
    const float* __restrict__ px_W1, const float* __restrict__ px_b1,
    const float* __restrict__ px_W2, const float* __restrict__ px_b2,
    const float* __restrict__ W_ih, const float* __restrict__ b_ih)
{
    __shared__ __align__(16) float s_pu1[64], s_px1[64];       // [c][i]
    __shared__ __align__(16) float s_pu2T[256], s_px2T[256];   // [k][c]
    __shared__ __align__(8)  float s_bu1[16], s_bu2[16], s_bx1[16], s_bx2[16];
    __shared__ unsigned s_emb[4][32 * EMB_STRIDE];             // per-warp [k][e] tf32

    const int tid  = threadIdx.x;
    const int lane = tid & 31;
    const int w    = tid >> 5;

    for (int i = tid; i < 64;  i += K1T) { s_pu1[i] = pu_W1[i]; s_px1[i] = px_W1[i]; }
    for (int i = tid; i < 256; i += K1T) {
        s_pu2T[(i & 15) * 16 + (i >> 4)] = pu_W2[i];
        s_px2T[(i & 15) * 16 + (i >> 4)] = px_W2[i];
    }
    if (tid < 16) { s_bu1[tid] = pu_b1[tid]; s_bu2[tid] = pu_b2[tid];
                    s_bx1[tid] = px_b1[tid]; s_bx2[tid] = px_b2[tid]; }

    const int gq = lane >> 2, tq = lane & 3;
    unsigned af[3][4][4];
    float bih0[3], bih8[3];
#pragma unroll
    for (int mt = 0; mt < 3; mt++) {
        const int r0 = mt * 16 + gq;
#pragma unroll
        for (int kt = 0; kt < 4; kt++) {
            const int c0 = kt * 8 + tq;
            af[mt][kt][0] = cvt_tf32(W_ih[r0 * 32 + c0]);
            af[mt][kt][1] = cvt_tf32(W_ih[(r0 + 8) * 32 + c0]);
            af[mt][kt][2] = cvt_tf32(W_ih[r0 * 32 + c0 + 4]);
            af[mt][kt][3] = cvt_tf32(W_ih[(r0 + 8) * 32 + c0 + 4]);
        }
        bih0[mt] = b_ih[r0];
        bih8[mt] = b_ih[r0 + 8];
    }
    __syncthreads();

    const int e = blockIdx.x * K1T + tid;

    float ue[16], xe[16];
    {
        const float4 u = *(const float4*)(u_in + (size_t)e * 4);
        float t[16];
#pragma unroll
        for (int c = 0; c < 16; c++) {
            const float4 wt = *(const float4*)&s_pu1[c * 4];
            t[c] = mytanh(fmaf(wt.x, u.x, fmaf(wt.y, u.y, fmaf(wt.z, u.z, fmaf(wt.w, u.w, s_bu1[c])))));
        }
        u64 a8[8];
#pragma unroll
        for (int j = 0; j < 8; j++) a8[j] = *(const u64*)&s_bu2[2 * j];
#pragma unroll
        for (int k = 0; k < 16; k++) {
            const u64 d2 = pk2(t[k], t[k]);
            const ulonglong2* row = (const ulonglong2*)&s_pu2T[k * 16];
#pragma unroll
            for (int q = 0; q < 4; q++) {
                const ulonglong2 wv = row[q];
                a8[2*q]   = ffma2(wv.x, d2, a8[2*q]);
                a8[2*q+1] = ffma2(wv.y, d2, a8[2*q+1]);
            }
        }
#pragma unroll
        for (int j = 0; j < 8; j++) upk2(ue[2*j], ue[2*j+1], a8[j]);
#pragma unroll
        for (int c = 0; c < 16; c++) ue[c] = mytanh(ue[c]);
    }
    {
        const float4 x = *(const float4*)(x_in + (size_t)e * 4);
        float t[16];
#pragma unroll
        for (int c = 0; c < 16; c++) {
            const float4 wt = *(const float4*)&s_px1[c * 4];
            t[c] = mytanh(fmaf(wt.x, x.x, fmaf(wt.y, x.y, fmaf(wt.z, x.z, fmaf(wt.w, x.w, s_bx1[c])))));
        }
        u64 a8[8];
#pragma unroll
        for (int j = 0; j < 8; j++) a8[j] = *(const u64*)&s_bx2[2 * j];
#pragma unroll
        for (int k = 0; k < 16; k++) {
            const u64 d2 = pk2(t[k], t[k]);
            const ulonglong2* row = (const ulonglong2*)&s_px2T[k * 16];
#pragma unroll
            for (int q = 0; q < 4; q++) {
                const ulonglong2 wv = row[q];
                a8[2*q]   = ffma2(wv.x, d2, a8[2*q]);
                a8[2*q+1] = ffma2(wv.y, d2, a8[2*q+1]);
            }
        }
#pragma unroll
        for (int j = 0; j < 8; j++) upk2(xe[2*j], xe[2*j+1], a8[j]);
#pragma unroll
        for (int c = 0; c < 16; c++) xe[c] = mytanh(xe[c]);
    }

    unsigned* se = s_emb[w];
#pragma unroll
    for (int c = 0; c < 16; c++) {
        se[c * EMB_STRIDE + lane]        = cvt_tf32(ue[c]);
        se[(16 + c) * EMB_STRIDE + lane] = cvt_tf32(xe[c]);
    }
    __syncwarp();

    const int tg0 = (blockIdx.x * K1T + w * 32) >> 3;
#pragma unroll
    for (int mt = 0; mt < 3; mt++) {
#pragma unroll
        for (int nt = 0; nt < 4; nt++) {
            float c[4] = {bih0[mt], bih0[mt], bih8[mt], bih8[mt]};
#pragma unroll
            for (int kt = 0; kt < 4; kt++) {
                const unsigned b0 = se[(kt * 8 + tq) * EMB_STRIDE + nt * 8 + gq];
                const unsigned b1 = se[(kt * 8 + 4 + tq) * EMB_STRIDE + nt * 8 + gq];
                mma_tf32(c, af[mt][kt], b0, b1);
            }
            float4* dst = (float4*)(g_gates + ((size_t)(tg0 + nt) * 3 + mt) * 128);
            dst[lane] = make_float4(c[0], c[1], c[2], c[3]);
        }
    }
}

// ============================================================================
// K2: lean GRU recurrence (no decoder). h_prev in a register; gate inputs
// prefetched 8 deep and pre-transformed into ex2-ready form off the chain:
//   pr = -log2e * xr, pz = -log2e * xz, pn = -2*log2e * xn, (xn kept raw? no)
// sigmoid(a) = rcp(1 + ex2(fma(-log2e, dot, pr)))
// n = 2*rcp(1 + ex2(fma(r, -2*log2e*hn_dot, pn))) - 1
// ============================================================================
#define BPC 14
#define NT2 (BPC * 16)
#define TILE_STRIDE_L ((B_ / 8) * 384)

__global__ void __launch_bounds__(NT2, 1) k2_recur(
    const float* __restrict__ W_hh, const float* __restrict__ b_hh,
    float* __restrict__ out_h)
{
    __shared__ __align__(16) float s_h[2][BPC][16];
    const int tid = threadIdx.x, lane = tid & 15, g = tid >> 4;
    const int b = blockIdx.x * BPC + g;
    const bool active = (b < B_);
    const int bb = active ? b : (B_ - 1);

    u64 vrp[8], vzp[8], vnp[8];
#pragma unroll
    for (int j = 0; j < 8; j++) {
        vrp[j] = *(const u64*)&W_hh[lane * 16 + 2 * j];
        vzp[j] = *(const u64*)&W_hh[(16 + lane) * 16 + 2 * j];
        vnp[j] = *(const u64*)&W_hh[(32 + lane) * 16 + 2 * j];
    }
    const float bhr = b_hh[lane], bhz = b_hh[16 + lane], bhn = b_hh[32 + lane];

    s_h[0][g][lane] = 0.f;
    s_h[1][g][lane] = 0.f;
    __syncthreads();

    // fragment-layout gate addressing (loop-invariant)
    const int cc = bb & 7;
    const int off = (lane & 7) * 16 + ((cc >> 1) << 2) + ((lane >> 3) << 1) + (cc & 1);
    const float* gb = g_gates + (size_t)(bb >> 3) * 384 + off;

    // 8-deep ring, pre-transformed for the ex2 chain
    float cr[8], cz[8], cn[8], nr[8], nz[8], nn_[8];
#pragma unroll
    for (int j = 0; j < 8; j++) {
        const float* gp = gb + (size_t)j * TILE_STRIDE_L;
        cr[j] = -LOG2E * gp[0];
        cz[j] = -LOG2E * gp[128];
        cn[j] = (-2.0f * LOG2E) * gp[256];
    }

    float hcur = 0.f;
    for (int blk = 0; blk < L_ / 8; blk++) {
#pragma unroll
        for (int j = 0; j < 8; j++) {
            const int l = blk * 8 + j;
            if (blk < L_ / 8 - 1) {
                const float* gp = gb + (size_t)(l + 8) * TILE_STRIDE_L;
                nr[j] = -LOG2E * gp[0];
                nz[j] = -LOG2E * gp[128];
                nn_[j] = (-2.0f * LOG2E) * gp[256];
            }
            const int p = j & 1;
            const ulonglong2* sh = (const ulonglong2*)s_h[p][g];
            const ulonglong2 q0 = sh[0], q1 = sh[1], q2 = sh[2], q3 = sh[3];
            const u64 hhp[8] = {q0.x, q0.y, q1.x, q1.y, q2.x, q2.y, q3.x, q3.y};
            const float h_prev = hcur;
            if (active) out_h[((size_t)l * B_ + bb) * 16 + lane] = h_prev;

            // split-accumulator dots
            u64 ar0 = pk2(bhr, 0.f), az0 = pk2(bhz, 0.f), an0 = pk2(bhn, 0.f);
            u64 ar1 = pk2(0.f, 0.f), az1 = ar1, an1 = ar1;
#pragma unroll
            for (int k = 0; k < 4; k++) {
                ar0 = ffma2(vrp[k], hhp[k], ar0);
                az0 = ffma2(vzp[k], hhp[k], az0);
                an0 = ffma2(vnp[k], hhp[k], an0);
            }
#pragma unroll
            for (int k = 4; k < 8; k++) {
                ar1 = ffma2(vrp[k], hhp[k], ar1);
                az1 = ffma2(vzp[k], hhp[k], az1);
                an1 = ffma2(vnp[k], hhp[k], an1);
            }
            float rl, rh, zl, zh, nl, nh;
            upk2(rl, rh, fadd2(ar0, ar1));
            upk2(zl, zh, fadd2(az0, az1));
            upk2(nl, nh, fadd2(an0, an1));
            const float dotr = rl + rh, dotz = zl + zh, dotn = nl + nh;

            const float r = rcpf(1.0f + ex2f(fmaf(-LOG2E, dotr, cr[j])));
            const float z = rcpf(1.0f + ex2f(fmaf(-LOG2E, dotz, cz[j])));
            const float hnscaled = (-2.0f * LOG2E) * dotn;   // overlaps r chain
            const float en = ex2f(fmaf(r, hnscaled, cn[j]));
            const float n = fmaf(2.0f, rcpf(1.0f + en), -1.0f);
            const float h_new = fmaf(z, h_prev - n, n);
            hcur = h_new;
            s_h[1 - p][g][lane] = h_new;
            __syncwarp();
        }
#pragma unroll
        for (int j = 0; j < 8; j++) { cr[j] = nr[j]; cz[j] = nz[j]; cn[j] = nn_[j]; }
    }
    if (active) g_hlast[(size_t)bb * 16 + lane] = hcur;
}

// ============================================================================
// K3: decoder MLP on every post-step hidden — fully parallel, f32x2 dots.
// h_all[l] = out_h[l+1] for l < L-1, else g_hlast.
// ============================================================================
__global__ void __launch_bounds__(256) k3_dec(
    const float* __restrict__ dec_W1, const float* __restrict__ dec_b1,
    const float* __restrict__ dec_W2, const float* __restrict__ dec_b2,
    const float* __restrict__ out_h, float* __restrict__ out_x)
{
    __shared__ __align__(16) float s_d1[512];   // dec_W1 [32][16] row-major
    __shared__ __align__(16) float s_d2[128];   // dec_W2 [4][32] row-major
    __shared__ float s_b1[32];
    __shared__ float s_b2[4];
    const int tid = threadIdx.x;
    for (int i = tid; i < 512; i += 256) s_d1[i] = dec_W1[i];
    if (tid < 128) s_d2[tid] = dec_W2[tid];
    if (tid < 32)  s_b1[tid] = dec_b1[tid];
    if (tid < 4)   s_b2[tid] = dec_b2[tid];
    __syncthreads();

    const int e = blockIdx.x * 256 + tid;
    const int l = e >> 11;
    const int b = e & (B_ - 1);
    const float* hp = (l < L_ - 1) ? (out_h + ((size_t)e + B_) * 16)
                                   : (g_hlast + (size_t)b * 16);
    u64 hh[8];
    {
        const ulonglong2 a = *(const ulonglong2*)(hp + 0);
        const ulonglong2 bq = *(const ulonglong2*)(hp + 4);
        const ulonglong2 cq = *(const ulonglong2*)(hp + 8);
        const ulonglong2 dq = *(const ulonglong2*)(hp + 12);
        hh[0] = a.x; hh[1] = a.y; hh[2] = bq.x; hh[3] = bq.y;
        hh[4] = cq.x; hh[5] = cq.y; hh[6] = dq.x; hh[7] = dq.y;
    }

    float o0 = s_b2[0], o1 = s_b2[1], o2 = s_b2[2], o3 = s_b2[3];
#pragma unroll
    for (int j = 0; j < 32; j++) {
        u64 a0 = pk2(s_b1[j], 0.f), a1 = pk2(0.f, 0.f);
        const ulonglong2* row = (const ulonglong2*)&s_d1[j * 16];
        const ulonglong2 w0 = row[0], w1 = row[1], w2 = row[2], w3 = row[3];
        a0 = ffma2(w0.x, hh[0], a0); a1 = ffma2(w0.y, hh[1], a1);
        a0 = ffma2(w1.x, hh[2], a0); a1 = ffma2(w1.y, hh[3], a1);
        a0 = ffma2(w2.x, hh[4], a0); a1 = ffma2(w2.y, hh[5], a1);
        a0 = ffma2(w3.x, hh[6], a0); a1 = ffma2(w3.y, hh[7], a1);
        float lo, hi; upk2(lo, hi, fadd2(a0, a1));
        const float d = mytanh(lo + hi);
        o0 = fmaf(s_d2[j],      d, o0);
        o1 = fmaf(s_d2[32 + j], d, o1);
        o2 = fmaf(s_d2[64 + j], d, o2);
        o3 = fmaf(s_d2[96 + j], d, o3);
    }
    *(float4*)(out_x + (size_t)e * 4) = make_float4(o0, o1, o2, o3);
}

// ============================================================================
extern "C" void kernel_launch(void* const* d_in, const int* in_sizes, int n_in,
                              void* d_out, int out_size) {
    const float* u_in   = (const float*)d_in[0];
    const float* x_in   = (const float*)d_in[1];
    const float* pu_W1  = (const float*)d_in[2];
    const float* pu_b1  = (const float*)d_in[3];
    const float* pu_W2  = (const float*)d_in[4];
    const float* pu_b2  = (const float*)d_in[5];
    const float* px_W1  = (const float*)d_in[6];
    const float* px_b1  = (const float*)d_in[7];
    const float* px_W2  = (const float*)d_in[8];
    const float* px_b2  = (const float*)d_in[9];
    const float* W_ih   = (const float*)d_in[10];
    const float* b_ih   = (const float*)d_in[11];
    const float* W_hh   = (const float*)d_in[12];
    const float* b_hh   = (const float*)d_in[13];
    const float* dec_W1 = (const float*)d_in[14];
    const float* dec_b1 = (const float*)d_in[15];
    const float* dec_W2 = (const float*)d_in[16];
    const float* dec_b2 = (const float*)d_in[17];

    float* out_x = (float*)d_out;                          // [L,B,4]
    float* out_h = (float*)d_out + (size_t)L_ * B_ * 4;    // [L,B,16]

    k1_gates<<<NE / K1T, K1T>>>(u_in, x_in, pu_W1, pu_b1, pu_W2, pu_b2,
                                px_W1, px_b1, px_W2, px_b2, W_ih, b_ih);
    k2_recur<<<(B_ + BPC - 1) / BPC, NT2>>>(W_hh, b_hh, out_h);
    k3_dec<<<NE / 256, 256>>>(dec_W1, dec_b1, dec_W2, dec_b2, out_h, out_x);
}

// round 9
// speedup vs baseline: 1.0212x; 1.0212x over previous
#include <cuda_runtime.h>
#include <cstdint>

typedef unsigned long long u64;

#define L_ 1024
#define B_ 2048
#define NE (L_ * B_)

// scratch: gate pre-activations, layout [e/8][48][8]:
//   offset(e, g) = (e>>3)*384 + g*8 + (e&7)
__device__ float g_gates[(size_t)NE * 48];

#define LOG2E 1.4426950408889634f

__device__ __forceinline__ float ex2f(float x) {
    float y; asm("ex2.approx.f32 %0, %1;" : "=f"(y) : "f"(x)); return y;
}
__device__ __forceinline__ float rcpf(float x) {
    float y; asm("rcp.approx.f32 %0, %1;" : "=f"(y) : "f"(x)); return y;
}
__device__ __forceinline__ float sigf(float x) {
    return rcpf(1.0f + ex2f(-LOG2E * x));
}
__device__ __forceinline__ float mytanh(float x) {
    return fmaf(2.0f, sigf(2.0f * x), -1.0f);
}

// ---- packed f32x2 helpers ----
__device__ __forceinline__ u64 pk2(float lo, float hi) {
    u64 r; asm("mov.b64 %0, {%1, %2};" : "=l"(r) : "f"(lo), "f"(hi)); return r;
}
__device__ __forceinline__ void upk2(float& lo, float& hi, u64 v) {
    asm("mov.b64 {%0, %1}, %2;" : "=f"(lo), "=f"(hi) : "l"(v));
}
__device__ __forceinline__ u64 ffma2(u64 a, u64 b, u64 c) {
    u64 d; asm("fma.rn.f32x2 %0, %1, %2, %3;" : "=l"(d) : "l"(a), "l"(b), "l"(c)); return d;
}
__device__ __forceinline__ u64 fadd2(u64 a, u64 b) {
    u64 d; asm("add.rn.f32x2 %0, %1, %2;" : "=l"(d) : "l"(a), "l"(b)); return d;
}
__device__ __forceinline__ u64 fmul2(u64 a, u64 b) {
    u64 d; asm("mul.rn.f32x2 %0, %1, %2;" : "=l"(d) : "l"(a), "l"(b)); return d;
}
__device__ __forceinline__ unsigned cvt_tf32(float f) {
    unsigned r; asm("cvt.rna.tf32.f32 %0, %1;" : "=r"(r) : "f"(f)); return r;
}
__device__ __forceinline__ void mma_tf32(float* c, const unsigned* a, unsigned b0, unsigned b1) {
    asm volatile(
        "mma.sync.aligned.m16n8k8.row.col.f32.tf32.tf32.f32 "
        "{%0,%1,%2,%3}, {%4,%5,%6,%7}, {%8,%9}, {%0,%1,%2,%3};"
        : "+f"(c[0]), "+f"(c[1]), "+f"(c[2]), "+f"(c[3])
        : "r"(a[0]), "r"(a[1]), "r"(a[2]), "r"(a[3]), "r"(b0), "r"(b1));
}

// ============================================================================
// K1: preprocess MLPs (fp32) + gate GEMM on tensor cores. Fragments written
// as element-pairs (STG.64, 256B-contiguous per instruction) into [e/8][48][8].
// ============================================================================
#define K1T 128
#define EMB_STRIDE 36

__global__ void __launch_bounds__(K1T, 4) k1_gates(
    const float* __restrict__ u_in, const float* __restrict__ x_in,
    const float* __restrict__ pu_W1, const float* __restrict__ pu_b1,
    const float* __restrict__ pu_W2, const float* __restrict__ pu_b2,
    const float* __restrict__ px_W1, const float* __restrict__ px_b1,
    const float* __restrict__ px_W2, const float* __restrict__ px_b2,
    const float* __restrict__ W_ih, const float* __restrict__ b_ih)
{
    __shared__ __align__(16) float s_pu1[64], s_px1[64];       // [c][i]
    __shared__ __align__(16) float s_pu2T[256], s_px2T[256];   // [k][c]
    __shared__ __align__(8)  float s_bu1[16], s_bu2[16], s_bx1[16], s_bx2[16];
    __shared__ unsigned s_emb[4][32 * EMB_STRIDE];             // per-warp [k][e] tf32

    const int tid  = threadIdx.x;
    const int lane = tid & 31;
    const int w    = tid >> 5;

    for (int i = tid; i < 64;  i += K1T) { s_pu1[i] = pu_W1[i]; s_px1[i] = px_W1[i]; }
    for (int i = tid; i < 256; i += K1T) {
        s_pu2T[(i & 15) * 16 + (i >> 4)] = pu_W2[i];
        s_px2T[(i & 15) * 16 + (i >> 4)] = px_W2[i];
    }
    if (tid < 16) { s_bu1[tid] = pu_b1[tid]; s_bu2[tid] = pu_b2[tid];
                    s_bx1[tid] = px_b1[tid]; s_bx2[tid] = px_b2[tid]; }

    const int gq = lane >> 2, tq = lane & 3;
    unsigned af[3][4][4];
    float bih0[3], bih8[3];
#pragma unroll
    for (int mt = 0; mt < 3; mt++) {
        const int r0 = mt * 16 + gq;
#pragma unroll
        for (int kt = 0; kt < 4; kt++) {
            const int c0 = kt * 8 + tq;
            af[mt][kt][0] = cvt_tf32(W_ih[r0 * 32 + c0]);
            af[mt][kt][1] = cvt_tf32(W_ih[(r0 + 8) * 32 + c0]);
            af[mt][kt][2] = cvt_tf32(W_ih[r0 * 32 + c0 + 4]);
            af[mt][kt][3] = cvt_tf32(W_ih[(r0 + 8) * 32 + c0 + 4]);
        }
        bih0[mt] = b_ih[r0];
        bih8[mt] = b_ih[r0 + 8];
    }
    __syncthreads();

    const int e = blockIdx.x * K1T + tid;

    float ue[16], xe[16];
    {
        const float4 u = *(const float4*)(u_in + (size_t)e * 4);
        float t[16];
#pragma unroll
        for (int c = 0; c < 16; c++) {
            const float4 wt = *(const float4*)&s_pu1[c * 4];
            t[c] = mytanh(fmaf(wt.x, u.x, fmaf(wt.y, u.y, fmaf(wt.z, u.z, fmaf(wt.w, u.w, s_bu1[c])))));
        }
        u64 a8[8];
#pragma unroll
        for (int j = 0; j < 8; j++) a8[j] = *(const u64*)&s_bu2[2 * j];
#pragma unroll
        for (int k = 0; k < 16; k++) {
            const u64 d2 = pk2(t[k], t[k]);
            const ulonglong2* row = (const ulonglong2*)&s_pu2T[k * 16];
#pragma unroll
            for (int q = 0; q < 4; q++) {
                const ulonglong2 wv = row[q];
                a8[2*q]   = ffma2(wv.x, d2, a8[2*q]);
                a8[2*q+1] = ffma2(wv.y, d2, a8[2*q+1]);
            }
        }
#pragma unroll
        for (int j = 0; j < 8; j++) upk2(ue[2*j], ue[2*j+1], a8[j]);
#pragma unroll
        for (int c = 0; c < 16; c++) ue[c] = mytanh(ue[c]);
    }
    {
        const float4 x = *(const float4*)(x_in + (size_t)e * 4);
        float t[16];
#pragma unroll
        for (int c = 0; c < 16; c++) {
            const float4 wt = *(const float4*)&s_px1[c * 4];
            t[c] = mytanh(fmaf(wt.x, x.x, fmaf(wt.y, x.y, fmaf(wt.z, x.z, fmaf(wt.w, x.w, s_bx1[c])))));
        }
        u64 a8[8];
#pragma unroll
        for (int j = 0; j < 8; j++) a8[j] = *(const u64*)&s_bx2[2 * j];
#pragma unroll
        for (int k = 0; k < 16; k++) {
            const u64 d2 = pk2(t[k], t[k]);
            const ulonglong2* row = (const ulonglong2*)&s_px2T[k * 16];
#pragma unroll
            for (int q = 0; q < 4; q++) {
                const ulonglong2 wv = row[q];
                a8[2*q]   = ffma2(wv.x, d2, a8[2*q]);
                a8[2*q+1] = ffma2(wv.y, d2, a8[2*q+1]);
            }
        }
#pragma unroll
        for (int j = 0; j < 8; j++) upk2(xe[2*j], xe[2*j+1], a8[j]);
#pragma unroll
        for (int c = 0; c < 16; c++) xe[c] = mytanh(xe[c]);
    }

    unsigned* se = s_emb[w];
#pragma unroll
    for (int c = 0; c < 16; c++) {
        se[c * EMB_STRIDE + lane]        = cvt_tf32(ue[c]);
        se[(16 + c) * EMB_STRIDE + lane] = cvt_tf32(xe[c]);
    }
    __syncwarp();

    const int oct0 = (blockIdx.x * K1T + w * 32) >> 3;   // first element-octet
#pragma unroll
    for (int mt = 0; mt < 3; mt++) {
#pragma unroll
        for (int nt = 0; nt < 4; nt++) {
            float c[4] = {bih0[mt], bih0[mt], bih8[mt], bih8[mt]};
#pragma unroll
            for (int kt = 0; kt < 4; kt++) {
                const unsigned b0 = se[(kt * 8 + tq) * EMB_STRIDE + nt * 8 + gq];
                const unsigned b1 = se[(kt * 8 + 4 + tq) * EMB_STRIDE + nt * 8 + gq];
                mma_tf32(c, af[mt][kt], b0, b1);
            }
            // c0,c1 = (row, e),(row, e+1); c2,c3 = (row+8, e),(row+8, e+1); e&7 = 2*tq
            u64* t64 = (u64*)(g_gates + (size_t)(oct0 + nt) * 384);
            t64[(mt * 16 + gq) * 4 + tq]     = pk2(c[0], c[1]);
            t64[(mt * 16 + gq + 8) * 4 + tq] = pk2(c[2], c[3]);
        }
    }
}

// ============================================================================
// K2: fused GRU recurrence + decoder (R4 structure, proven 301us) with:
//   - h_prev kept in a register (no dependent scalar LDS)
//   - gate inputs pre-folded into ex2-ready constants off the critical path
//   - [e/8][48][8] gate addressing (strides +0/+128/+256 like R4)
// ============================================================================
#define BPC 14
#define NT2 (BPC * 16)
#define TILE_STRIDE_L ((B_ / 8) * 384)

__global__ void __launch_bounds__(NT2, 1) k2_recur(
    const float* __restrict__ W_hh, const float* __restrict__ b_hh,
    const float* __restrict__ dec_W1, const float* __restrict__ dec_b1,
    const float* __restrict__ dec_W2, const float* __restrict__ dec_b2,
    float* __restrict__ out_h, float* __restrict__ out_x)
{
    __shared__ __align__(16) float s_h[2][BPC][16];
    const int tid = threadIdx.x, lane = tid & 15, g = tid >> 4;
    const int b = blockIdx.x * BPC + g;
    const bool active = (b < B_);
    const int bb = active ? b : (B_ - 1);

    u64 vrp[8], vzp[8], vnp[8];
#pragma unroll
    for (int j = 0; j < 8; j++) {
        vrp[j] = *(const u64*)&W_hh[lane * 16 + 2 * j];
        vzp[j] = *(const u64*)&W_hh[(16 + lane) * 16 + 2 * j];
        vnp[j] = *(const u64*)&W_hh[(32 + lane) * 16 + 2 * j];
    }
    const float bhr = b_hh[lane], bhz = b_hh[16 + lane], bhn = b_hh[32 + lane];

    u64 wd0[8], wd1[8];
#pragma unroll
    for (int j = 0; j < 8; j++) {
        wd0[j] = *(const u64*)&dec_W1[(2 * lane) * 16 + 2 * j];
        wd1[j] = *(const u64*)&dec_W1[(2 * lane + 1) * 16 + 2 * j];
    }
    const float db1_0 = dec_b1[2 * lane], db1_1 = dec_b1[2 * lane + 1];
    u64 w2p[4];
#pragma unroll
    for (int o = 0; o < 4; o++) w2p[o] = *(const u64*)&dec_W2[o * 32 + 2 * lane];
    const float db2 = dec_b2[lane & 3];

    s_h[0][g][lane] = 0.f;
    s_h[1][g][lane] = 0.f;
    __syncthreads();

    // [e/8][48][8] addressing, loop-invariant
    const float* gb = g_gates + (size_t)(bb >> 3) * 384 + lane * 8 + (bb & 7);

    // 8-deep ring, pre-transformed for the ex2 chain
    float cr[8], cz[8], cn[8], nr[8], nz[8], nn_[8];
#pragma unroll
    for (int j = 0; j < 8; j++) {
        const float* gp = gb + (size_t)j * TILE_STRIDE_L;
        cr[j] = -LOG2E * gp[0];
        cz[j] = -LOG2E * gp[128];
        cn[j] = (-2.0f * LOG2E) * gp[256];
    }

    float hcur = 0.f;
    for (int blk = 0; blk < L_ / 8; blk++) {
#pragma unroll
        for (int j = 0; j < 8; j++) {
            const int l = blk * 8 + j;
            if (blk < L_ / 8 - 1) {
                const float* gp = gb + (size_t)(l + 8) * TILE_STRIDE_L;
                nr[j] = -LOG2E * gp[0];
                nz[j] = -LOG2E * gp[128];
                nn_[j] = (-2.0f * LOG2E) * gp[256];
            }
            const int p = j & 1;
            const ulonglong2* sh = (const ulonglong2*)s_h[p][g];
            const ulonglong2 q0 = sh[0], q1 = sh[1], q2 = sh[2], q3 = sh[3];
            const u64 hhp[8] = {q0.x, q0.y, q1.x, q1.y, q2.x, q2.y, q3.x, q3.y};
            const float h_prev = hcur;
            if (active) out_h[((size_t)l * B_ + bb) * 16 + lane] = h_prev;

            // ---- recurrence (critical path), split accumulators ----
            u64 ar0 = pk2(bhr, 0.f), az0 = pk2(bhz, 0.f), an0 = pk2(bhn, 0.f);
            u64 ar1 = pk2(0.f, 0.f), az1 = ar1, an1 = ar1;
#pragma unroll
            for (int k = 0; k < 4; k++) {
                ar0 = ffma2(vrp[k], hhp[k], ar0);
                az0 = ffma2(vzp[k], hhp[k], az0);
                an0 = ffma2(vnp[k], hhp[k], an0);
            }
#pragma unroll
            for (int k = 4; k < 8; k++) {
                ar1 = ffma2(vrp[k], hhp[k], ar1);
                az1 = ffma2(vzp[k], hhp[k], az1);
                an1 = ffma2(vnp[k], hhp[k], an1);
            }
            float rl, rh, zl, zh, nl, nh;
            upk2(rl, rh, fadd2(ar0, ar1));
            upk2(zl, zh, fadd2(az0, az1));
            upk2(nl, nh, fadd2(an0, an1));
            const float r = rcpf(1.0f + ex2f(fmaf(-LOG2E, rl + rh, cr[j])));
            const float z = rcpf(1.0f + ex2f(fmaf(-LOG2E, zl + zh, cz[j])));
            const float hnscaled = (-2.0f * LOG2E) * (nl + nh);
            const float en = ex2f(fmaf(r, hnscaled, cn[j]));
            const float n = fmaf(2.0f, rcpf(1.0f + en), -1.0f);
            const float h_new = fmaf(z, h_prev - n, n);
            hcur = h_new;
            s_h[1 - p][g][lane] = h_new;

            // ---- decoder on hhp == h_all[l-1] → out_x[l-1] ----
            u64 aD0 = pk2(db1_0, 0.f), aD1 = pk2(db1_1, 0.f);
#pragma unroll
            for (int k = 0; k < 8; k++) {
                aD0 = ffma2(wd0[k], hhp[k], aD0);
                aD1 = ffma2(wd1[k], hhp[k], aD1);
            }
            float d0l, d0h, d1l, d1h;
            upk2(d0l, d0h, aD0); upk2(d1l, d1h, aD1);
            const float d0 = mytanh(d0l + d0h);
            const float d1 = mytanh(d1l + d1h);
            const u64 dpk = pk2(d0, d1);
            float pp0, pp1, pp2, pp3;
            { float lo, hi;
              upk2(lo, hi, fmul2(w2p[0], dpk)); pp0 = lo + hi;
              upk2(lo, hi, fmul2(w2p[1], dpk)); pp1 = lo + hi;
              upk2(lo, hi, fmul2(w2p[2], dpk)); pp2 = lo + hi;
              upk2(lo, hi, fmul2(w2p[3], dpk)); pp3 = lo + hi; }
            float q01  = (lane & 1) ? pp1 : pp0;
            float q01b = (lane & 1) ? pp0 : pp1;
            q01 += __shfl_xor_sync(0xffffffffu, q01b, 1);
            float q23  = (lane & 1) ? pp3 : pp2;
            float q23b = (lane & 1) ? pp2 : pp3;
            q23 += __shfl_xor_sync(0xffffffffu, q23b, 1);
            float qq  = (lane & 2) ? q23 : q01;
            float qqb = (lane & 2) ? q01 : q23;
            qq += __shfl_xor_sync(0xffffffffu, qqb, 2);
            qq += __shfl_xor_sync(0xffffffffu, qq, 4);
            qq += __shfl_xor_sync(0xffffffffu, qq, 8);
            if (l > 0 && active && lane < 4)
                out_x[((size_t)(l - 1) * B_ + bb) * 4 + lane] = qq + db2;

            __syncwarp();
        }
#pragma unroll
        for (int j = 0; j < 8; j++) { cr[j] = nr[j]; cz[j] = nz[j]; cn[j] = nn_[j]; }
    }

    // tail: decode final hidden (in s_h[0]) → out_x[L-1]
    {
        const ulonglong2* sh = (const ulonglong2*)s_h[0][g];
        const ulonglong2 q0 = sh[0], q1 = sh[1], q2 = sh[2], q3 = sh[3];
        const u64 hhp[8] = {q0.x, q0.y, q1.x, q1.y, q2.x, q2.y, q3.x, q3.y};
        u64 aD0 = pk2(db1_0, 0.f), aD1 = pk2(db1_1, 0.f);
#pragma unroll
        for (int k = 0; k < 8; k++) {
            aD0 = ffma2(wd0[k], hhp[k], aD0);
            aD1 = ffma2(wd1[k], hhp[k], aD1);
        }
        float d0l, d0h, d1l, d1h;
        upk2(d0l, d0h, aD0); upk2(d1l, d1h, aD1);
        const float d0 = mytanh(d0l + d0h);
        const float d1 = mytanh(d1l + d1h);
        const u64 dpk = pk2(d0, d1);
        float pp0, pp1, pp2, pp3;
        { float lo, hi;
          upk2(lo, hi, fmul2(w2p[0], dpk)); pp0 = lo + hi;
          upk2(lo, hi, fmul2(w2p[1], dpk)); pp1 = lo + hi;
          upk2(lo, hi, fmul2(w2p[2], dpk)); pp2 = lo + hi;
          upk2(lo, hi, fmul2(w2p[3], dpk)); pp3 = lo + hi; }
        float q01  = (lane & 1) ? pp1 : pp0;
        float q01b = (lane & 1) ? pp0 : pp1;
        q01 += __shfl_xor_sync(0xffffffffu, q01b, 1);
        float q23  = (lane & 1) ? pp3 : pp2;
        float q23b = (lane & 1) ? pp2 : pp3;
        q23 += __shfl_xor_sync(0xffffffffu, q23b, 1);
        float qq  = (lane & 2) ? q23 : q01;
        float qqb = (lane & 2) ? q01 : q23;
        qq += __shfl_xor_sync(0xffffffffu, qqb, 2);
        qq += __shfl_xor_sync(0xffffffffu, qq, 4);
        qq += __shfl_xor_sync(0xffffffffu, qq, 8);
        if (active && lane < 4)
            out_x[((size_t)(L_ - 1) * B_ + bb) * 4 + lane] = qq + db2;
    }
}

// ============================================================================
extern "C" void kernel_launch(void* const* d_in, const int* in_sizes, int n_in,
                              void* d_out, int out_size) {
    const float* u_in   = (const float*)d_in[0];
    const float* x_in   = (const float*)d_in[1];
    const float* pu_W1  = (const float*)d_in[2];
    const float* pu_b1  = (const float*)d_in[3];
    const float* pu_W2  = (const float*)d_in[4];
    const float* pu_b2  = (const float*)d_in[5];
    const float* px_W1  = (const float*)d_in[6];
    const float* px_b1  = (const float*)d_in[7];
    const float* px_W2  = (const float*)d_in[8];
    const float* px_b2  = (const float*)d_in[9];
    const float* W_ih   = (const float*)d_in[10];
    const float* b_ih   = (const float*)d_in[11];
    const float* W_hh   = (const float*)d_in[12];
    const float* b_hh   = (const float*)d_in[13];
    const float* dec_W1 = (const float*)d_in[14];
    const float* dec_b1 = (const float*)d_in[15];
    const float* dec_W2 = (const float*)d_in[16];
    const float* dec_b2 = (const float*)d_in[17];

    float* out_x = (float*)d_out;                          // [L,B,4]
    float* out_h = (float*)d_out + (size_t)L_ * B_ * 4;    // [L,B,16]

    k1_gates<<<NE / K1T, K1T>>>(u_in, x_in, pu_W1, pu_b1, pu_W2, pu_b2,
                                px_W1, px_b1, px_W2, px_b2, W_ih, b_ih);
    k2_recur<<<(B_ + BPC - 1) / BPC, NT2>>>(W_hh, b_hh,
                                            dec_W1, dec_b1, dec_W2, dec_b2,
                                            out_h, out_x);
}

// round 10
// speedup vs baseline: 1.2849x; 1.2582x over previous
#include <cuda_runtime.h>
#include <cstdint>

typedef unsigned long long u64;

#define L_ 1024
#define B_ 2048
#define NE (L_ * B_)

// scratch: gate pre-activations in HMMA fragment-tile layout:
// tile t = (e/8), gate-block mt = g/16 → 128-float tile in fragment order
//   offset(r = g%16, c = e%8) = (r&7)*16 + (c>>1)*4 + ((r>>3)<<1) + (c&1)
__device__ float g_gates[(size_t)NE * 48];

__device__ __forceinline__ float ex2f(float x) {
    float y; asm("ex2.approx.f32 %0, %1;" : "=f"(y) : "f"(x)); return y;
}
__device__ __forceinline__ float rcpf(float x) {
    float y; asm("rcp.approx.f32 %0, %1;" : "=f"(y) : "f"(x)); return y;
}
__device__ __forceinline__ float sigf(float x) {
    return rcpf(1.0f + ex2f(-1.4426950408889634f * x));
}
__device__ __forceinline__ float mytanh(float x) {
    return fmaf(2.0f, sigf(2.0f * x), -1.0f);
}

// ---- packed f32x2 helpers ----
__device__ __forceinline__ u64 pk2(float lo, float hi) {
    u64 r; asm("mov.b64 %0, {%1, %2};" : "=l"(r) : "f"(lo), "f"(hi)); return r;
}
__device__ __forceinline__ void upk2(float& lo, float& hi, u64 v) {
    asm("mov.b64 {%0, %1}, %2;" : "=f"(lo), "=f"(hi) : "l"(v));
}
__device__ __forceinline__ u64 ffma2(u64 a, u64 b, u64 c) {
    u64 d; asm("fma.rn.f32x2 %0, %1, %2, %3;" : "=l"(d) : "l"(a), "l"(b), "l"(c)); return d;
}
__device__ __forceinline__ u64 fmul2(u64 a, u64 b) {
    u64 d; asm("mul.rn.f32x2 %0, %1, %2;" : "=l"(d) : "l"(a), "l"(b)); return d;
}
__device__ __forceinline__ unsigned cvt_tf32(float f) {
    unsigned r; asm("cvt.rna.tf32.f32 %0, %1;" : "=r"(r) : "f"(f)); return r;
}
__device__ __forceinline__ void mma_tf32(float* c, const unsigned* a, unsigned b0, unsigned b1) {
    asm volatile(
        "mma.sync.aligned.m16n8k8.row.col.f32.tf32.tf32.f32 "
        "{%0,%1,%2,%3}, {%4,%5,%6,%7}, {%8,%9}, {%0,%1,%2,%3};"
        : "+f"(c[0]), "+f"(c[1]), "+f"(c[2]), "+f"(c[3])
        : "r"(a[0]), "r"(a[1]), "r"(a[2]), "r"(a[3]), "r"(b0), "r"(b1));
}

// ============================================================================
// K1 (R8 verbatim): preprocess MLPs (fp32) + gate GEMM on tensor cores;
// fragments stored directly in fragment-tile layout (coalesced STG.128).
// ============================================================================
#define K1T 128
#define EMB_STRIDE 36

__global__ void __launch_bounds__(K1T, 4) k1_gates(
    const float* __restrict__ u_in, const float* __restrict__ x_in,
    const float* __restrict__ pu_W1, const float* __restrict__ pu_b1,
    const float* __restrict__ pu_W2, const float* __restrict__ pu_b2,
    const float* __restrict__ px_W1, const float* __restrict__ px_b1,
    const float* __restrict__ px_W2, const float* __restrict__ px_b2,
    const float* __restrict__ W_ih, const float* __restrict__ b_ih)
{
    __shared__ __align__(16) float s_pu1[64], s_px1[64];       // [c][i]
    __shared__ __align__(16) float s_pu2T[256], s_px2T[256];   // [k][c]
    __shared__ __align__(8)  float s_bu1[16], s_bu2[16], s_bx1[16], s_bx2[16];
    __shared__ unsigned s_emb[4][32 * EMB_STRIDE];             // per-warp [k][e] tf32

    const int tid  = threadIdx.x;
    const int lane = tid & 31;
    const int w    = tid >> 5;

    for (int i = tid; i < 64;  i += K1T) { s_pu1[i] = pu_W1[i]; s_px1[i] = px_W1[i]; }
    for (int i = tid; i < 256; i += K1T) {
        s_pu2T[(i & 15) * 16 + (i >> 4)] = pu_W2[i];
        s_px2T[(i & 15) * 16 + (i >> 4)] = px_W2[i];
    }
    if (tid < 16) { s_bu1[tid] = pu_b1[tid]; s_bu2[tid] = pu_b2[tid];
                    s_bx1[tid] = px_b1[tid]; s_bx2[tid] = px_b2[tid]; }

    const int gq = lane >> 2, tq = lane & 3;
    unsigned af[3][4][4];
    float bih0[3], bih8[3];
#pragma unroll
    for (int mt = 0; mt < 3; mt++) {
        const int r0 = mt * 16 + gq;
#pragma unroll
        for (int kt = 0; kt < 4; kt++) {
            const int c0 = kt * 8 + tq;
            af[mt][kt][0] = cvt_tf32(W_ih[r0 * 32 + c0]);
            af[mt][kt][1] = cvt_tf32(W_ih[(r0 + 8) * 32 + c0]);
            af[mt][kt][2] = cvt_tf32(W_ih[r0 * 32 + c0 + 4]);
            af[mt][kt][3] = cvt_tf32(W_ih[(r0 + 8) * 32 + c0 + 4]);
        }
        bih0[mt] = b_ih[r0];
        bih8[mt] = b_ih[r0 + 8];
    }
    __syncthreads();

    const int e = blockIdx.x * K1T + tid;

    float ue[16], xe[16];
    {
        const float4 u = *(const float4*)(u_in + (size_t)e * 4);
        float t[16];
#pragma unroll
        for (int c = 0; c < 16; c++) {
            const float4 wt = *(const float4*)&s_pu1[c * 4];
            t[c] = mytanh(fmaf(wt.x, u.x, fmaf(wt.y, u.y, fmaf(wt.z, u.z, fmaf(wt.w, u.w, s_bu1[c])))));
        }
        u64 a8[8];
#pragma unroll
        for (int j = 0; j < 8; j++) a8[j] = *(const u64*)&s_bu2[2 * j];
#pragma unroll
        for (int k = 0; k < 16; k++) {
            const u64 d2 = pk2(t[k], t[k]);
            const ulonglong2* row = (const ulonglong2*)&s_pu2T[k * 16];
#pragma unroll
            for (int q = 0; q < 4; q++) {
                const ulonglong2 wv = row[q];
                a8[2*q]   = ffma2(wv.x, d2, a8[2*q]);
                a8[2*q+1] = ffma2(wv.y, d2, a8[2*q+1]);
            }
        }
#pragma unroll
        for (int j = 0; j < 8; j++) upk2(ue[2*j], ue[2*j+1], a8[j]);
#pragma unroll
        for (int c = 0; c < 16; c++) ue[c] = mytanh(ue[c]);
    }
    {
        const float4 x = *(const float4*)(x_in + (size_t)e * 4);
        float t[16];
#pragma unroll
        for (int c = 0; c < 16; c++) {
            const float4 wt = *(const float4*)&s_px1[c * 4];
            t[c] = mytanh(fmaf(wt.x, x.x, fmaf(wt.y, x.y, fmaf(wt.z, x.z, fmaf(wt.w, x.w, s_bx1[c])))));
        }
        u64 a8[8];
#pragma unroll
        for (int j = 0; j < 8; j++) a8[j] = *(const u64*)&s_bx2[2 * j];
#pragma unroll
        for (int k = 0; k < 16; k++) {
            const u64 d2 = pk2(t[k], t[k]);
            const ulonglong2* row = (const ulonglong2*)&s_px2T[k * 16];
#pragma unroll
            for (int q = 0; q < 4; q++) {
                const ulonglong2 wv = row[q];
                a8[2*q]   = ffma2(wv.x, d2, a8[2*q]);
                a8[2*q+1] = ffma2(wv.y, d2, a8[2*q+1]);
            }
        }
#pragma unroll
        for (int j = 0; j < 8; j++) upk2(xe[2*j], xe[2*j+1], a8[j]);
#pragma unroll
        for (int c = 0; c < 16; c++) xe[c] = mytanh(xe[c]);
    }

    unsigned* se = s_emb[w];
#pragma unroll
    for (int c = 0; c < 16; c++) {
        se[c * EMB_STRIDE + lane]        = cvt_tf32(ue[c]);
        se[(16 + c) * EMB_STRIDE + lane] = cvt_tf32(xe[c]);
    }
    __syncwarp();

    const int tg0 = (blockIdx.x * K1T + w * 32) >> 3;
#pragma unroll
    for (int mt = 0; mt < 3; mt++) {
#pragma unroll
        for (int nt = 0; nt < 4; nt++) {
            float c[4] = {bih0[mt], bih0[mt], bih8[mt], bih8[mt]};
#pragma unroll
            for (int kt = 0; kt < 4; kt++) {
                const unsigned b0 = se[(kt * 8 + tq) * EMB_STRIDE + nt * 8 + gq];
                const unsigned b1 = se[(kt * 8 + 4 + tq) * EMB_STRIDE + nt * 8 + gq];
                mma_tf32(c, af[mt][kt], b0, b1);
            }
            float4* dst = (float4*)(g_gates + ((size_t)(tg0 + nt) * 3 + mt) * 128);
            dst[lane] = make_float4(c[0], c[1], c[2], c[3]);
        }
    }
}

// ============================================================================
// K2 (R4 verbatim, proven 301us): fused GRU recurrence + decoder. Only change:
// gate-load addressing adapted to the fragment-tile layout (loop-invariant
// offset; strides +0/+128/+256 exactly as in R4).
// ============================================================================
#define BPC 14
#define NT2 (BPC * 16)
#define TILE_STRIDE_L ((B_ / 8) * 384)

__global__ void __launch_bounds__(NT2, 1) k2_recur(
    const float* __restrict__ W_hh, const float* __restrict__ b_hh,
    const float* __restrict__ dec_W1, const float* __restrict__ dec_b1,
    const float* __restrict__ dec_W2, const float* __restrict__ dec_b2,
    float* __restrict__ out_h, float* __restrict__ out_x)
{
    __shared__ __align__(16) float s_h[2][BPC][16];
    const int tid = threadIdx.x, lane = tid & 15, g = tid >> 4;
    const int b = blockIdx.x * BPC + g;
    const bool active = (b < B_);
    const int bb = active ? b : (B_ - 1);

    u64 vrp[8], vzp[8], vnp[8];
#pragma unroll
    for (int j = 0; j < 8; j++) {
        vrp[j] = *(const u64*)&W_hh[lane * 16 + 2 * j];
        vzp[j] = *(const u64*)&W_hh[(16 + lane) * 16 + 2 * j];
        vnp[j] = *(const u64*)&W_hh[(32 + lane) * 16 + 2 * j];
    }
    const float bhr = b_hh[lane], bhz = b_hh[16 + lane], bhn = b_hh[32 + lane];

    u64 wd0[8], wd1[8];
#pragma unroll
    for (int j = 0; j < 8; j++) {
        wd0[j] = *(const u64*)&dec_W1[(2 * lane) * 16 + 2 * j];
        wd1[j] = *(const u64*)&dec_W1[(2 * lane + 1) * 16 + 2 * j];
    }
    const float db1_0 = dec_b1[2 * lane], db1_1 = dec_b1[2 * lane + 1];
    u64 w2p[4];
#pragma unroll
    for (int o = 0; o < 4; o++) w2p[o] = *(const u64*)&dec_W2[o * 32 + 2 * lane];
    const float db2 = dec_b2[lane & 3];

    s_h[0][g][lane] = 0.f;
    s_h[1][g][lane] = 0.f;
    __syncthreads();

    // fragment-layout gate addressing (loop-invariant)
    const int cc = bb & 7;
    const int off = (lane & 7) * 16 + ((cc >> 1) << 2) + ((lane >> 3) << 1) + (cc & 1);
    const float* gb = g_gates + (size_t)(bb >> 3) * 384 + off;

    float cr[8], cz[8], cn[8], nr[8], nz[8], nn_[8];
#pragma unroll
    for (int j = 0; j < 8; j++) {
        const float* gp = gb + (size_t)j * TILE_STRIDE_L;
        cr[j] = gp[0]; cz[j] = gp[128]; cn[j] = gp[256];
    }

    for (int blk = 0; blk < L_ / 8; blk++) {
#pragma unroll
        for (int j = 0; j < 8; j++) {
            const int l = blk * 8 + j;
            if (blk < L_ / 8 - 1) {
                const float* gp = gb + (size_t)(l + 8) * TILE_STRIDE_L;
                nr[j] = gp[0]; nz[j] = gp[128]; nn_[j] = gp[256];
            }
            const int p = j & 1;
            const ulonglong2* sh = (const ulonglong2*)s_h[p][g];
            const ulonglong2 q0 = sh[0], q1 = sh[1], q2 = sh[2], q3 = sh[3];
            const u64 hhp[8] = {q0.x, q0.y, q1.x, q1.y, q2.x, q2.y, q3.x, q3.y};
            const float h_prev = s_h[p][g][lane];
            if (active) out_h[((size_t)l * B_ + bb) * 16 + lane] = h_prev;

            u64 ar = pk2(bhr, 0.f), az = pk2(bhz, 0.f), an = pk2(bhn, 0.f);
#pragma unroll
            for (int k = 0; k < 8; k++) {
                ar = ffma2(vrp[k], hhp[k], ar);
                az = ffma2(vzp[k], hhp[k], az);
                an = ffma2(vnp[k], hhp[k], an);
            }
            float rl, rh, zl, zh, nl, nh;
            upk2(rl, rh, ar); upk2(zl, zh, az); upk2(nl, nh, an);
            const float r = sigf(cr[j] + (rl + rh));
            const float z = sigf(cz[j] + (zl + zh));
            const float n = mytanh(fmaf(r, nl + nh, cn[j]));
            const float h_new = fmaf(z, h_prev - n, n);
            s_h[1 - p][g][lane] = h_new;

            // decoder on hhp == h_all[l-1] → out_x[l-1]
            u64 aD0 = pk2(db1_0, 0.f), aD1 = pk2(db1_1, 0.f);
#pragma unroll
            for (int k = 0; k < 8; k++) {
                aD0 = ffma2(wd0[k], hhp[k], aD0);
                aD1 = ffma2(wd1[k], hhp[k], aD1);
            }
            float d0l, d0h, d1l, d1h;
            upk2(d0l, d0h, aD0); upk2(d1l, d1h, aD1);
            const float d0 = mytanh(d0l + d0h);
            const float d1 = mytanh(d1l + d1h);
            const u64 dpk = pk2(d0, d1);
            float pp0, pp1, pp2, pp3;
            { float lo, hi;
              upk2(lo, hi, fmul2(w2p[0], dpk)); pp0 = lo + hi;
              upk2(lo, hi, fmul2(w2p[1], dpk)); pp1 = lo + hi;
              upk2(lo, hi, fmul2(w2p[2], dpk)); pp2 = lo + hi;
              upk2(lo, hi, fmul2(w2p[3], dpk)); pp3 = lo + hi; }
            float q01  = (lane & 1) ? pp1 : pp0;
            float q01b = (lane & 1) ? pp0 : pp1;
            q01 += __shfl_xor_sync(0xffffffffu, q01b, 1);
            float q23  = (lane & 1) ? pp3 : pp2;
            float q23b = (lane & 1) ? pp2 : pp3;
            q23 += __shfl_xor_sync(0xffffffffu, q23b, 1);
            float qq  = (lane & 2) ? q23 : q01;
            float qqb = (lane & 2) ? q01 : q23;
            qq += __shfl_xor_sync(0xffffffffu, qqb, 2);
            qq += __shfl_xor_sync(0xffffffffu, qq, 4);
            qq += __shfl_xor_sync(0xffffffffu, qq, 8);
            if (l > 0 && active && lane < 4)
                out_x[((size_t)(l - 1) * B_ + bb) * 4 + lane] = qq + db2;

            __syncwarp();
        }
#pragma unroll
        for (int j = 0; j < 8; j++) { cr[j] = nr[j]; cz[j] = nz[j]; cn[j] = nn_[j]; }
    }

    // tail: decode final hidden (in s_h[0]) → out_x[L-1]
    {
        const ulonglong2* sh = (const ulonglong2*)s_h[0][g];
        const ulonglong2 q0 = sh[0], q1 = sh[1], q2 = sh[2], q3 = sh[3];
        const u64 hhp[8] = {q0.x, q0.y, q1.x, q1.y, q2.x, q2.y, q3.x, q3.y};
        u64 aD0 = pk2(db1_0, 0.f), aD1 = pk2(db1_1, 0.f);
#pragma unroll
        for (int k = 0; k < 8; k++) {
            aD0 = ffma2(wd0[k], hhp[k], aD0);
            aD1 = ffma2(wd1[k], hhp[k], aD1);
        }
        float d0l, d0h, d1l, d1h;
        upk2(d0l, d0h, aD0); upk2(d1l, d1h, aD1);
        const float d0 = mytanh(d0l + d0h);
        const float d1 = mytanh(d1l + d1h);
        const u64 dpk = pk2(d0, d1);
        float pp0, pp1, pp2, pp3;
        { float lo, hi;
          upk2(lo, hi, fmul2(w2p[0], dpk)); pp0 = lo + hi;
          upk2(lo, hi, fmul2(w2p[1], dpk)); pp1 = lo + hi;
          upk2(lo, hi, fmul2(w2p[2], dpk)); pp2 = lo + hi;
          upk2(lo, hi, fmul2(w2p[3], dpk)); pp3 = lo + hi; }
        float q01  = (lane & 1) ? pp1 : pp0;
        float q01b = (lane & 1) ? pp0 : pp1;
        q01 += __shfl_xor_sync(0xffffffffu, q01b, 1);
        float q23  = (lane & 1) ? pp3 : pp2;
        float q23b = (lane & 1) ? pp2 : pp3;
        q23 += __shfl_xor_sync(0xffffffffu, q23b, 1);
        float qq  = (lane & 2) ? q23 : q01;
        float qqb = (lane & 2) ? q01 : q23;
        qq += __shfl_xor_sync(0xffffffffu, qqb, 2);
        qq += __shfl_xor_sync(0xffffffffu, qq, 4);
        qq += __shfl_xor_sync(0xffffffffu, qq, 8);
        if (active && lane < 4)
            out_x[((size_t)(L_ - 1) * B_ + bb) * 4 + lane] = qq + db2;
    }
}

// ============================================================================
extern "C" void kernel_launch(void* const* d_in, const int* in_sizes, int n_in,
                              void* d_out, int out_size) {
    const float* u_in   = (const float*)d_in[0];
    const float* x_in   = (const float*)d_in[1];
    const float* pu_W1  = (const float*)d_in[2];
    const float* pu_b1  = (const float*)d_in[3];
    const float* pu_W2  = (const float*)d_in[4];
    const float* pu_b2  = (const float*)d_in[5];
    const float* px_W1  = (const float*)d_in[6];
    const float* px_b1  = (const float*)d_in[7];
    const float* px_W2  = (const float*)d_in[8];
    const float* px_b2  = (const float*)d_in[9];
    const float* W_ih   = (const float*)d_in[10];
    const float* b_ih   = (const float*)d_in[11];
    const float* W_hh   = (const float*)d_in[12];
    const float* b_hh   = (const float*)d_in[13];
    const float* dec_W1 = (const float*)d_in[14];
    const float* dec_b1 = (const float*)d_in[15];
    const float* dec_W2 = (const float*)d_in[16];
    const float* dec_b2 = (const float*)d_in[17];

    float* out_x = (float*)d_out;                          // [L,B,4]
    float* out_h = (float*)d_out + (size_t)L_ * B_ * 4;    // [L,B,16]

    k1_gates<<<NE / K1T, K1T>>>(u_in, x_in, pu_W1, pu_b1, pu_W2, pu_b2,
                                px_W1, px_b1, px_W2, px_b2, W_ih, b_ih);
    k2_recur<<<(B_ + BPC - 1) / BPC, NT2>>>(W_hh, b_hh,
                                            dec_W1, dec_b1, dec_W2, dec_b2,
                                            out_h, out_x);
}

// round 11
// speedup vs baseline: 1.3443x; 1.0462x over previous
#include <cuda_runtime.h>
#include <cstdint>

typedef unsigned long long u64;

#define L_ 1024
#define B_ 2048
#define NE (L_ * B_)

// scratch: gate pre-activations in HMMA fragment-tile layout:
// tile t = (e/8), gate-block mt = g/16 → 128-float tile in fragment order
//   offset(r = g%16, c = e%8) = (r&7)*16 + (c>>1)*4 + ((r>>3)<<1) + (c&1)
__device__ float g_gates[(size_t)NE * 48];

__device__ __forceinline__ float ex2f(float x) {
    float y; asm("ex2.approx.f32 %0, %1;" : "=f"(y) : "f"(x)); return y;
}
__device__ __forceinline__ float rcpf(float x) {
    float y; asm("rcp.approx.f32 %0, %1;" : "=f"(y) : "f"(x)); return y;
}
__device__ __forceinline__ float sigf(float x) {
    return rcpf(1.0f + ex2f(-1.4426950408889634f * x));
}
__device__ __forceinline__ float mytanh(float x) {
    return fmaf(2.0f, sigf(2.0f * x), -1.0f);
}
// single-MUFU tanh (sm_75+); used ONLY off the recurrence feedback path
__device__ __forceinline__ float tanha(float x) {
    float y; asm("tanh.approx.f32 %0, %1;" : "=f"(y) : "f"(x)); return y;
}

// ---- packed f32x2 helpers ----
__device__ __forceinline__ u64 pk2(float lo, float hi) {
    u64 r; asm("mov.b64 %0, {%1, %2};" : "=l"(r) : "f"(lo), "f"(hi)); return r;
}
__device__ __forceinline__ void upk2(float& lo, float& hi, u64 v) {
    asm("mov.b64 {%0, %1}, %2;" : "=f"(lo), "=f"(hi) : "l"(v));
}
__device__ __forceinline__ u64 ffma2(u64 a, u64 b, u64 c) {
    u64 d; asm("fma.rn.f32x2 %0, %1, %2, %3;" : "=l"(d) : "l"(a), "l"(b), "l"(c)); return d;
}
__device__ __forceinline__ u64 fmul2(u64 a, u64 b) {
    u64 d; asm("mul.rn.f32x2 %0, %1, %2;" : "=l"(d) : "l"(a), "l"(b)); return d;
}
__device__ __forceinline__ unsigned cvt_tf32(float f) {
    unsigned r; asm("cvt.rna.tf32.f32 %0, %1;" : "=r"(r) : "f"(f)); return r;
}
__device__ __forceinline__ void mma_tf32(float* c, const unsigned* a, unsigned b0, unsigned b1) {
    asm volatile(
        "mma.sync.aligned.m16n8k8.row.col.f32.tf32.tf32.f32 "
        "{%0,%1,%2,%3}, {%4,%5,%6,%7}, {%8,%9}, {%0,%1,%2,%3};"
        : "+f"(c[0]), "+f"(c[1]), "+f"(c[2]), "+f"(c[3])
        : "r"(a[0]), "r"(a[1]), "r"(a[2]), "r"(a[3]), "r"(b0), "r"(b1));
}

// ============================================================================
// K1: preprocess MLPs (fp32) + gate GEMM on tensor cores; fragments stored
// directly in fragment-tile layout (coalesced STG.128). B fragments hoisted
// per nt and reused across all 3 mt blocks (96 → 32 scalar LDS per thread).
// ============================================================================
#define K1T 128
#define EMB_STRIDE 36

__global__ void __launch_bounds__(K1T, 4) k1_gates(
    const float* __restrict__ u_in, const float* __restrict__ x_in,
    const float* __restrict__ pu_W1, const float* __restrict__ pu_b1,
    const float* __restrict__ pu_W2, const float* __restrict__ pu_b2,
    const float* __restrict__ px_W1, const float* __restrict__ px_b1,
    const float* __restrict__ px_W2, const float* __restrict__ px_b2,
    const float* __restrict__ W_ih, const float* __restrict__ b_ih)
{
    __shared__ __align__(16) float s_pu1[64], s_px1[64];       // [c][i]
    __shared__ __align__(16) float s_pu2T[256], s_px2T[256];   // [k][c]
    __shared__ __align__(8)  float s_bu1[16], s_bu2[16], s_bx1[16], s_bx2[16];
    __shared__ unsigned s_emb[4][32 * EMB_STRIDE];             // per-warp [k][e] tf32

    const int tid  = threadIdx.x;
    const int lane = tid & 31;
    const int w    = tid >> 5;

    for (int i = tid; i < 64;  i += K1T) { s_pu1[i] = pu_W1[i]; s_px1[i] = px_W1[i]; }
    for (int i = tid; i < 256; i += K1T) {
        s_pu2T[(i & 15) * 16 + (i >> 4)] = pu_W2[i];
        s_px2T[(i & 15) * 16 + (i >> 4)] = px_W2[i];
    }
    if (tid < 16) { s_bu1[tid] = pu_b1[tid]; s_bu2[tid] = pu_b2[tid];
                    s_bx1[tid] = px_b1[tid]; s_bx2[tid] = px_b2[tid]; }

    const int gq = lane >> 2, tq = lane & 3;
    unsigned af[3][4][4];
    float bih0[3], bih8[3];
#pragma unroll
    for (int mt = 0; mt < 3; mt++) {
        const int r0 = mt * 16 + gq;
#pragma unroll
        for (int kt = 0; kt < 4; kt++) {
            const int c0 = kt * 8 + tq;
            af[mt][kt][0] = cvt_tf32(W_ih[r0 * 32 + c0]);
            af[mt][kt][1] = cvt_tf32(W_ih[(r0 + 8) * 32 + c0]);
            af[mt][kt][2] = cvt_tf32(W_ih[r0 * 32 + c0 + 4]);
            af[mt][kt][3] = cvt_tf32(W_ih[(r0 + 8) * 32 + c0 + 4]);
        }
        bih0[mt] = b_ih[r0];
        bih8[mt] = b_ih[r0 + 8];
    }
    __syncthreads();

    const int e = blockIdx.x * K1T + tid;

    float ue[16], xe[16];
    {
        const float4 u = *(const float4*)(u_in + (size_t)e * 4);
        float t[16];
#pragma unroll
        for (int c = 0; c < 16; c++) {
            const float4 wt = *(const float4*)&s_pu1[c * 4];
            t[c] = mytanh(fmaf(wt.x, u.x, fmaf(wt.y, u.y, fmaf(wt.z, u.z, fmaf(wt.w, u.w, s_bu1[c])))));
        }
        u64 a8[8];
#pragma unroll
        for (int j = 0; j < 8; j++) a8[j] = *(const u64*)&s_bu2[2 * j];
#pragma unroll
        for (int k = 0; k < 16; k++) {
            const u64 d2 = pk2(t[k], t[k]);
            const ulonglong2* row = (const ulonglong2*)&s_pu2T[k * 16];
#pragma unroll
            for (int q = 0; q < 4; q++) {
                const ulonglong2 wv = row[q];
                a8[2*q]   = ffma2(wv.x, d2, a8[2*q]);
                a8[2*q+1] = ffma2(wv.y, d2, a8[2*q+1]);
            }
        }
#pragma unroll
        for (int j = 0; j < 8; j++) upk2(ue[2*j], ue[2*j+1], a8[j]);
#pragma unroll
        for (int c = 0; c < 16; c++) ue[c] = mytanh(ue[c]);
    }
    {
        const float4 x = *(const float4*)(x_in + (size_t)e * 4);
        float t[16];
#pragma unroll
        for (int c = 0; c < 16; c++) {
            const float4 wt = *(const float4*)&s_px1[c * 4];
            t[c] = mytanh(fmaf(wt.x, x.x, fmaf(wt.y, x.y, fmaf(wt.z, x.z, fmaf(wt.w, x.w, s_bx1[c])))));
        }
        u64 a8[8];
#pragma unroll
        for (int j = 0; j < 8; j++) a8[j] = *(const u64*)&s_bx2[2 * j];
#pragma unroll
        for (int k = 0; k < 16; k++) {
            const u64 d2 = pk2(t[k], t[k]);
            const ulonglong2* row = (const ulonglong2*)&s_px2T[k * 16];
#pragma unroll
            for (int q = 0; q < 4; q++) {
                const ulonglong2 wv = row[q];
                a8[2*q]   = ffma2(wv.x, d2, a8[2*q]);
                a8[2*q+1] = ffma2(wv.y, d2, a8[2*q+1]);
            }
        }
#pragma unroll
        for (int j = 0; j < 8; j++) upk2(xe[2*j], xe[2*j+1], a8[j]);
#pragma unroll
        for (int c = 0; c < 16; c++) xe[c] = mytanh(xe[c]);
    }

    unsigned* se = s_emb[w];
#pragma unroll
    for (int c = 0; c < 16; c++) {
        se[c * EMB_STRIDE + lane]        = cvt_tf32(ue[c]);
        se[(16 + c) * EMB_STRIDE + lane] = cvt_tf32(xe[c]);
    }
    __syncwarp();

    const int tg0 = (blockIdx.x * K1T + w * 32) >> 3;
#pragma unroll
    for (int nt = 0; nt < 4; nt++) {
        // hoist B fragments for this nt (shared across all 3 mt blocks)
        unsigned bf0[4], bf1[4];
#pragma unroll
        for (int kt = 0; kt < 4; kt++) {
            bf0[kt] = se[(kt * 8 + tq) * EMB_STRIDE + nt * 8 + gq];
            bf1[kt] = se[(kt * 8 + 4 + tq) * EMB_STRIDE + nt * 8 + gq];
        }
#pragma unroll
        for (int mt = 0; mt < 3; mt++) {
            float c[4] = {bih0[mt], bih0[mt], bih8[mt], bih8[mt]};
#pragma unroll
            for (int kt = 0; kt < 4; kt++)
                mma_tf32(c, af[mt][kt], bf0[kt], bf1[kt]);
            float4* dst = (float4*)(g_gates + ((size_t)(tg0 + nt) * 3 + mt) * 128);
            dst[lane] = make_float4(c[0], c[1], c[2], c[3]);
        }
    }
}

// ============================================================================
// K2 (R4 structure, proven): fused GRU recurrence + decoder. Decoder tanh's
// use single-MUFU tanh.approx (off the recurrence feedback path); recurrence
// nonlinearities stay ex2/rcp-exact so out_h is unchanged.
// ============================================================================
#define BPC 14
#define NT2 (BPC * 16)
#define TILE_STRIDE_L ((B_ / 8) * 384)

__global__ void __launch_bounds__(NT2, 1) k2_recur(
    const float* __restrict__ W_hh, const float* __restrict__ b_hh,
    const float* __restrict__ dec_W1, const float* __restrict__ dec_b1,
    const float* __restrict__ dec_W2, const float* __restrict__ dec_b2,
    float* __restrict__ out_h, float* __restrict__ out_x)
{
    __shared__ __align__(16) float s_h[2][BPC][16];
    const int tid = threadIdx.x, lane = tid & 15, g = tid >> 4;
    const int b = blockIdx.x * BPC + g;
    const bool active = (b < B_);
    const int bb = active ? b : (B_ - 1);

    u64 vrp[8], vzp[8], vnp[8];
#pragma unroll
    for (int j = 0; j < 8; j++) {
        vrp[j] = *(const u64*)&W_hh[lane * 16 + 2 * j];
        vzp[j] = *(const u64*)&W_hh[(16 + lane) * 16 + 2 * j];
        vnp[j] = *(const u64*)&W_hh[(32 + lane) * 16 + 2 * j];
    }
    const float bhr = b_hh[lane], bhz = b_hh[16 + lane], bhn = b_hh[32 + lane];

    u64 wd0[8], wd1[8];
#pragma unroll
    for (int j = 0; j < 8; j++) {
        wd0[j] = *(const u64*)&dec_W1[(2 * lane) * 16 + 2 * j];
        wd1[j] = *(const u64*)&dec_W1[(2 * lane + 1) * 16 + 2 * j];
    }
    const float db1_0 = dec_b1[2 * lane], db1_1 = dec_b1[2 * lane + 1];
    u64 w2p[4];
#pragma unroll
    for (int o = 0; o < 4; o++) w2p[o] = *(const u64*)&dec_W2[o * 32 + 2 * lane];
    const float db2 = dec_b2[lane & 3];

    s_h[0][g][lane] = 0.f;
    s_h[1][g][lane] = 0.f;
    __syncthreads();

    // fragment-layout gate addressing (loop-invariant)
    const int cc = bb & 7;
    const int off = (lane & 7) * 16 + ((cc >> 1) << 2) + ((lane >> 3) << 1) + (cc & 1);
    const float* gb = g_gates + (size_t)(bb >> 3) * 384 + off;

    float cr[8], cz[8], cn[8], nr[8], nz[8], nn_[8];
#pragma unroll
    for (int j = 0; j < 8; j++) {
        const float* gp = gb + (size_t)j * TILE_STRIDE_L;
        cr[j] = gp[0]; cz[j] = gp[128]; cn[j] = gp[256];
    }

    for (int blk = 0; blk < L_ / 8; blk++) {
#pragma unroll
        for (int j = 0; j < 8; j++) {
            const int l = blk * 8 + j;
            if (blk < L_ / 8 - 1) {
                const float* gp = gb + (size_t)(l + 8) * TILE_STRIDE_L;
                nr[j] = gp[0]; nz[j] = gp[128]; nn_[j] = gp[256];
            }
            const int p = j & 1;
            const ulonglong2* sh = (const ulonglong2*)s_h[p][g];
            const ulonglong2 q0 = sh[0], q1 = sh[1], q2 = sh[2], q3 = sh[3];
            const u64 hhp[8] = {q0.x, q0.y, q1.x, q1.y, q2.x, q2.y, q3.x, q3.y};
            const float h_prev = s_h[p][g][lane];
            if (active) out_h[((size_t)l * B_ + bb) * 16 + lane] = h_prev;

            u64 ar = pk2(bhr, 0.f), az = pk2(bhz, 0.f), an = pk2(bhn, 0.f);
#pragma unroll
            for (int k = 0; k < 8; k++) {
                ar = ffma2(vrp[k], hhp[k], ar);
                az = ffma2(vzp[k], hhp[k], az);
                an = ffma2(vnp[k], hhp[k], an);
            }
            float rl, rh, zl, zh, nl, nh;
            upk2(rl, rh, ar); upk2(zl, zh, az); upk2(nl, nh, an);
            const float r = sigf(cr[j] + (rl + rh));
            const float z = sigf(cz[j] + (zl + zh));
            const float n = mytanh(fmaf(r, nl + nh, cn[j]));
            const float h_new = fmaf(z, h_prev - n, n);
            s_h[1 - p][g][lane] = h_new;

            // decoder on hhp == h_all[l-1] → out_x[l-1]
            u64 aD0 = pk2(db1_0, 0.f), aD1 = pk2(db1_1, 0.f);
#pragma unroll
            for (int k = 0; k < 8; k++) {
                aD0 = ffma2(wd0[k], hhp[k], aD0);
                aD1 = ffma2(wd1[k], hhp[k], aD1);
            }
            float d0l, d0h, d1l, d1h;
            upk2(d0l, d0h, aD0); upk2(d1l, d1h, aD1);
            const float d0 = tanha(d0l + d0h);
            const float d1 = tanha(d1l + d1h);
            const u64 dpk = pk2(d0, d1);
            float pp0, pp1, pp2, pp3;
            { float lo, hi;
              upk2(lo, hi, fmul2(w2p[0], dpk)); pp0 = lo + hi;
              upk2(lo, hi, fmul2(w2p[1], dpk)); pp1 = lo + hi;
              upk2(lo, hi, fmul2(w2p[2], dpk)); pp2 = lo + hi;
              upk2(lo, hi, fmul2(w2p[3], dpk)); pp3 = lo + hi; }
            float q01  = (lane & 1) ? pp1 : pp0;
            float q01b = (lane & 1) ? pp0 : pp1;
            q01 += __shfl_xor_sync(0xffffffffu, q01b, 1);
            float q23  = (lane & 1) ? pp3 : pp2;
            float q23b = (lane & 1) ? pp2 : pp3;
            q23 += __shfl_xor_sync(0xffffffffu, q23b, 1);
            float qq  = (lane & 2) ? q23 : q01;
            float qqb = (lane & 2) ? q01 : q23;
            qq += __shfl_xor_sync(0xffffffffu, qqb, 2);
            qq += __shfl_xor_sync(0xffffffffu, qq, 4);
            qq += __shfl_xor_sync(0xffffffffu, qq, 8);
            if (l > 0 && active && lane < 4)
                out_x[((size_t)(l - 1) * B_ + bb) * 4 + lane] = qq + db2;

            __syncwarp();
        }
#pragma unroll
        for (int j = 0; j < 8; j++) { cr[j] = nr[j]; cz[j] = nz[j]; cn[j] = nn_[j]; }
    }

    // tail: decode final hidden (in s_h[0]) → out_x[L-1]
    {
        const ulonglong2* sh = (const ulonglong2*)s_h[0][g];
        const ulonglong2 q0 = sh[0], q1 = sh[1], q2 = sh[2], q3 = sh[3];
        const u64 hhp[8] = {q0.x, q0.y, q1.x, q1.y, q2.x, q2.y, q3.x, q3.y};
        u64 aD0 = pk2(db1_0, 0.f), aD1 = pk2(db1_1, 0.f);
#pragma unroll
        for (int k = 0; k < 8; k++) {
            aD0 = ffma2(wd0[k], hhp[k], aD0);
            aD1 = ffma2(wd1[k], hhp[k], aD1);
        }
        float d0l, d0h, d1l, d1h;
        upk2(d0l, d0h, aD0); upk2(d1l, d1h, aD1);
        const float d0 = tanha(d0l + d0h);
        const float d1 = tanha(d1l + d1h);
        const u64 dpk = pk2(d0, d1);
        float pp0, pp1, pp2, pp3;
        { float lo, hi;
          upk2(lo, hi, fmul2(w2p[0], dpk)); pp0 = lo + hi;
          upk2(lo, hi, fmul2(w2p[1], dpk)); pp1 = lo + hi;
          upk2(lo, hi, fmul2(w2p[2], dpk)); pp2 = lo + hi;
          upk2(lo, hi, fmul2(w2p[3], dpk)); pp3 = lo + hi; }
        float q01  = (lane & 1) ? pp1 : pp0;
        float q01b = (lane & 1) ? pp0 : pp1;
        q01 += __shfl_xor_sync(0xffffffffu, q01b, 1);
        float q23  = (lane & 1) ? pp3 : pp2;
        float q23b = (lane & 1) ? pp2 : pp3;
        q23 += __shfl_xor_sync(0xffffffffu, q23b, 1);
        float qq  = (lane & 2) ? q23 : q01;
        float qqb = (lane & 2) ? q01 : q23;
        qq += __shfl_xor_sync(0xffffffffu, qqb, 2);
        qq += __shfl_xor_sync(0xffffffffu, qq, 4);
        qq += __shfl_xor_sync(0xffffffffu, qq, 8);
        if (active && lane < 4)
            out_x[((size_t)(L_ - 1) * B_ + bb) * 4 + lane] = qq + db2;
    }
}

// ============================================================================
extern "C" void kernel_launch(void* const* d_in, const int* in_sizes, int n_in,
                              void* d_out, int out_size) {
    const float* u_in   = (const float*)d_in[0];
    const float* x_in   = (const float*)d_in[1];
    const float* pu_W1  = (const float*)d_in[2];
    const float* pu_b1  = (const float*)d_in[3];
    const float* pu_W2  = (const float*)d_in[4];
    const float* pu_b2  = (const float*)d_in[5];
    const float* px_W1  = (const float*)d_in[6];
    const float* px_b1  = (const float*)d_in[7];
    const float* px_W2  = (const float*)d_in[8];
    const float* px_b2  = (const float*)d_in[9];
    const float* W_ih   = (const float*)d_in[10];
    const float* b_ih   = (const float*)d_in[11];
    const float* W_hh   = (const float*)d_in[12];
    const float* b_hh   = (const float*)d_in[13];
    const float* dec_W1 = (const float*)d_in[14];
    const float* dec_b1 = (const float*)d_in[15];
    const float* dec_W2 = (const float*)d_in[16];
    const float* dec_b2 = (const float*)d_in[17];

    float* out_x = (float*)d_out;                          // [L,B,4]
    float* out_h = (float*)d_out + (size_t)L_ * B_ * 4;    // [L,B,16]

    k1_gates<<<NE / K1T, K1T>>>(u_in, x_in, pu_W1, pu_b1, pu_W2, pu_b2,
                                px_W1, px_b1, px_W2, px_b2, W_ih, b_ih);
    k2_recur<<<(B_ + BPC - 1) / BPC, NT2>>>(W_hh, b_hh,
                                            dec_W1, dec_b1, dec_W2, dec_b2,
                                            out_h, out_x);
}

// round 12
// speedup vs baseline: 1.3707x; 1.0197x over previous
#include <cuda_runtime.h>
#include <cstdint>

typedef unsigned long long u64;

#define L_ 1024
#define B_ 2048
#define NE (L_ * B_)

// scratch: gate pre-activations in HMMA fragment-tile layout:
// tile t = (e/8), gate-block mt = g/16 → 128-float tile in fragment order
//   offset(r = g%16, c = e%8) = (r&7)*16 + (c>>1)*4 + ((r>>3)<<1) + (c&1)
__device__ float g_gates[(size_t)NE * 48];

__device__ __forceinline__ float ex2f(float x) {
    float y; asm("ex2.approx.f32 %0, %1;" : "=f"(y) : "f"(x)); return y;
}
__device__ __forceinline__ float rcpf(float x) {
    float y; asm("rcp.approx.f32 %0, %1;" : "=f"(y) : "f"(x)); return y;
}
__device__ __forceinline__ float sigf(float x) {
    return rcpf(1.0f + ex2f(-1.4426950408889634f * x));
}
__device__ __forceinline__ float mytanh(float x) {
    return fmaf(2.0f, sigf(2.0f * x), -1.0f);
}
// single-MUFU tanh (sm_75+); error ~2^-11 rel — at/below tf32 quantization.
// Used in k1 (feeds tf32 GEMM) and k2's decoder (off the recurrence path).
__device__ __forceinline__ float tanha(float x) {
    float y; asm("tanh.approx.f32 %0, %1;" : "=f"(y) : "f"(x)); return y;
}

// ---- packed f32x2 helpers ----
__device__ __forceinline__ u64 pk2(float lo, float hi) {
    u64 r; asm("mov.b64 %0, {%1, %2};" : "=l"(r) : "f"(lo), "f"(hi)); return r;
}
__device__ __forceinline__ void upk2(float& lo, float& hi, u64 v) {
    asm("mov.b64 {%0, %1}, %2;" : "=f"(lo), "=f"(hi) : "l"(v));
}
__device__ __forceinline__ u64 ffma2(u64 a, u64 b, u64 c) {
    u64 d; asm("fma.rn.f32x2 %0, %1, %2, %3;" : "=l"(d) : "l"(a), "l"(b), "l"(c)); return d;
}
__device__ __forceinline__ u64 fmul2(u64 a, u64 b) {
    u64 d; asm("mul.rn.f32x2 %0, %1, %2;" : "=l"(d) : "l"(a), "l"(b)); return d;
}
__device__ __forceinline__ unsigned cvt_tf32(float f) {
    unsigned r; asm("cvt.rna.tf32.f32 %0, %1;" : "=r"(r) : "f"(f)); return r;
}
__device__ __forceinline__ void mma_tf32(float* c, const unsigned* a, unsigned b0, unsigned b1) {
    asm volatile(
        "mma.sync.aligned.m16n8k8.row.col.f32.tf32.tf32.f32 "
        "{%0,%1,%2,%3}, {%4,%5,%6,%7}, {%8,%9}, {%0,%1,%2,%3};"
        : "+f"(c[0]), "+f"(c[1]), "+f"(c[2]), "+f"(c[3])
        : "r"(a[0]), "r"(a[1]), "r"(a[2]), "r"(a[3]), "r"(b0), "r"(b1));
}

// ============================================================================
// K1: preprocess MLPs (fp32, single-MUFU tanh) + gate GEMM on tensor cores;
// fragments stored directly in fragment-tile layout (coalesced STG.128).
// ============================================================================
#define K1T 128
#define EMB_STRIDE 36

__global__ void __launch_bounds__(K1T, 4) k1_gates(
    const float* __restrict__ u_in, const float* __restrict__ x_in,
    const float* __restrict__ pu_W1, const float* __restrict__ pu_b1,
    const float* __restrict__ pu_W2, const float* __restrict__ pu_b2,
    const float* __restrict__ px_W1, const float* __restrict__ px_b1,
    const float* __restrict__ px_W2, const float* __restrict__ px_b2,
    const float* __restrict__ W_ih, const float* __restrict__ b_ih)
{
    __shared__ __align__(16) float s_pu1[64], s_px1[64];       // [c][i]
    __shared__ __align__(16) float s_pu2T[256], s_px2T[256];   // [k][c]
    __shared__ __align__(8)  float s_bu1[16], s_bu2[16], s_bx1[16], s_bx2[16];
    __shared__ unsigned s_emb[4][32 * EMB_STRIDE];             // per-warp [k][e] tf32

    const int tid  = threadIdx.x;
    const int lane = tid & 31;
    const int w    = tid >> 5;

    for (int i = tid; i < 64;  i += K1T) { s_pu1[i] = pu_W1[i]; s_px1[i] = px_W1[i]; }
    for (int i = tid; i < 256; i += K1T) {
        s_pu2T[(i & 15) * 16 + (i >> 4)] = pu_W2[i];
        s_px2T[(i & 15) * 16 + (i >> 4)] = px_W2[i];
    }
    if (tid < 16) { s_bu1[tid] = pu_b1[tid]; s_bu2[tid] = pu_b2[tid];
                    s_bx1[tid] = px_b1[tid]; s_bx2[tid] = px_b2[tid]; }

    const int gq = lane >> 2, tq = lane & 3;
    unsigned af[3][4][4];
    float bih0[3], bih8[3];
#pragma unroll
    for (int mt = 0; mt < 3; mt++) {
        const int r0 = mt * 16 + gq;
#pragma unroll
        for (int kt = 0; kt < 4; kt++) {
            const int c0 = kt * 8 + tq;
            af[mt][kt][0] = cvt_tf32(W_ih[r0 * 32 + c0]);
            af[mt][kt][1] = cvt_tf32(W_ih[(r0 + 8) * 32 + c0]);
            af[mt][kt][2] = cvt_tf32(W_ih[r0 * 32 + c0 + 4]);
            af[mt][kt][3] = cvt_tf32(W_ih[(r0 + 8) * 32 + c0 + 4]);
        }
        bih0[mt] = b_ih[r0];
        bih8[mt] = b_ih[r0 + 8];
    }
    __syncthreads();

    const int e = blockIdx.x * K1T + tid;

    float ue[16], xe[16];
    {
        const float4 u = *(const float4*)(u_in + (size_t)e * 4);
        float t[16];
#pragma unroll
        for (int c = 0; c < 16; c++) {
            const float4 wt = *(const float4*)&s_pu1[c * 4];
            t[c] = tanha(fmaf(wt.x, u.x, fmaf(wt.y, u.y, fmaf(wt.z, u.z, fmaf(wt.w, u.w, s_bu1[c])))));
        }
        u64 a8[8];
#pragma unroll
        for (int j = 0; j < 8; j++) a8[j] = *(const u64*)&s_bu2[2 * j];
#pragma unroll
        for (int k = 0; k < 16; k++) {
            const u64 d2 = pk2(t[k], t[k]);
            const ulonglong2* row = (const ulonglong2*)&s_pu2T[k * 16];
#pragma unroll
            for (int q = 0; q < 4; q++) {
                const ulonglong2 wv = row[q];
                a8[2*q]   = ffma2(wv.x, d2, a8[2*q]);
                a8[2*q+1] = ffma2(wv.y, d2, a8[2*q+1]);
            }
        }
#pragma unroll
        for (int j = 0; j < 8; j++) upk2(ue[2*j], ue[2*j+1], a8[j]);
#pragma unroll
        for (int c = 0; c < 16; c++) ue[c] = tanha(ue[c]);
    }
    {
        const float4 x = *(const float4*)(x_in + (size_t)e * 4);
        float t[16];
#pragma unroll
        for (int c = 0; c < 16; c++) {
            const float4 wt = *(const float4*)&s_px1[c * 4];
            t[c] = tanha(fmaf(wt.x, x.x, fmaf(wt.y, x.y, fmaf(wt.z, x.z, fmaf(wt.w, x.w, s_bx1[c])))));
        }
        u64 a8[8];
#pragma unroll
        for (int j = 0; j < 8; j++) a8[j] = *(const u64*)&s_bx2[2 * j];
#pragma unroll
        for (int k = 0; k < 16; k++) {
            const u64 d2 = pk2(t[k], t[k]);
            const ulonglong2* row = (const ulonglong2*)&s_px2T[k * 16];
#pragma unroll
            for (int q = 0; q < 4; q++) {
                const ulonglong2 wv = row[q];
                a8[2*q]   = ffma2(wv.x, d2, a8[2*q]);
                a8[2*q+1] = ffma2(wv.y, d2, a8[2*q+1]);
            }
        }
#pragma unroll
        for (int j = 0; j < 8; j++) upk2(xe[2*j], xe[2*j+1], a8[j]);
#pragma unroll
        for (int c = 0; c < 16; c++) xe[c] = tanha(xe[c]);
    }

    unsigned* se = s_emb[w];
#pragma unroll
    for (int c = 0; c < 16; c++) {
        se[c * EMB_STRIDE + lane]        = cvt_tf32(ue[c]);
        se[(16 + c) * EMB_STRIDE + lane] = cvt_tf32(xe[c]);
    }
    __syncwarp();

    const int tg0 = (blockIdx.x * K1T + w * 32) >> 3;
#pragma unroll
    for (int nt = 0; nt < 4; nt++) {
        unsigned bf0[4], bf1[4];
#pragma unroll
        for (int kt = 0; kt < 4; kt++) {
            bf0[kt] = se[(kt * 8 + tq) * EMB_STRIDE + nt * 8 + gq];
            bf1[kt] = se[(kt * 8 + 4 + tq) * EMB_STRIDE + nt * 8 + gq];
        }
#pragma unroll
        for (int mt = 0; mt < 3; mt++) {
            float c[4] = {bih0[mt], bih0[mt], bih8[mt], bih8[mt]};
#pragma unroll
            for (int kt = 0; kt < 4; kt++)
                mma_tf32(c, af[mt][kt], bf0[kt], bf1[kt]);
            float4* dst = (float4*)(g_gates + ((size_t)(tg0 + nt) * 3 + mt) * 128);
            dst[lane] = make_float4(c[0], c[1], c[2], c[3]);
        }
    }
}

// ============================================================================
// K2 (unchanged from R11): fused GRU recurrence + decoder. Recurrence
// nonlinearities ex2/rcp-exact; decoder uses tanh.approx.
// ============================================================================
#define BPC 14
#define NT2 (BPC * 16)
#define TILE_STRIDE_L ((B_ / 8) * 384)

__global__ void __launch_bounds__(NT2, 1) k2_recur(
    const float* __restrict__ W_hh, const float* __restrict__ b_hh,
    const float* __restrict__ dec_W1, const float* __restrict__ dec_b1,
    const float* __restrict__ dec_W2, const float* __restrict__ dec_b2,
    float* __restrict__ out_h, float* __restrict__ out_x)
{
    __shared__ __align__(16) float s_h[2][BPC][16];
    const int tid = threadIdx.x, lane = tid & 15, g = tid >> 4;
    const int b = blockIdx.x * BPC + g;
    const bool active = (b < B_);
    const int bb = active ? b : (B_ - 1);

    u64 vrp[8], vzp[8], vnp[8];
#pragma unroll
    for (int j = 0; j < 8; j++) {
        vrp[j] = *(const u64*)&W_hh[lane * 16 + 2 * j];
        vzp[j] = *(const u64*)&W_hh[(16 + lane) * 16 + 2 * j];
        vnp[j] = *(const u64*)&W_hh[(32 + lane) * 16 + 2 * j];
    }
    const float bhr = b_hh[lane], bhz = b_hh[16 + lane], bhn = b_hh[32 + lane];

    u64 wd0[8], wd1[8];
#pragma unroll
    for (int j = 0; j < 8; j++) {
        wd0[j] = *(const u64*)&dec_W1[(2 * lane) * 16 + 2 * j];
        wd1[j] = *(const u64*)&dec_W1[(2 * lane + 1) * 16 + 2 * j];
    }
    const float db1_0 = dec_b1[2 * lane], db1_1 = dec_b1[2 * lane + 1];
    u64 w2p[4];
#pragma unroll
    for (int o = 0; o < 4; o++) w2p[o] = *(const u64*)&dec_W2[o * 32 + 2 * lane];
    const float db2 = dec_b2[lane & 3];

    s_h[0][g][lane] = 0.f;
    s_h[1][g][lane] = 0.f;
    __syncthreads();

    // fragment-layout gate addressing (loop-invariant)
    const int cc = bb & 7;
    const int off = (lane & 7) * 16 + ((cc >> 1) << 2) + ((lane >> 3) << 1) + (cc & 1);
    const float* gb = g_gates + (size_t)(bb >> 3) * 384 + off;

    float cr[8], cz[8], cn[8], nr[8], nz[8], nn_[8];
#pragma unroll
    for (int j = 0; j < 8; j++) {
        const float* gp = gb + (size_t)j * TILE_STRIDE_L;
        cr[j] = gp[0]; cz[j] = gp[128]; cn[j] = gp[256];
    }

    for (int blk = 0; blk < L_ / 8; blk++) {
#pragma unroll
        for (int j = 0; j < 8; j++) {
            const int l = blk * 8 + j;
            if (blk < L_ / 8 - 1) {
                const float* gp = gb + (size_t)(l + 8) * TILE_STRIDE_L;
                nr[j] = gp[0]; nz[j] = gp[128]; nn_[j] = gp[256];
            }
            const int p = j & 1;
            const ulonglong2* sh = (const ulonglong2*)s_h[p][g];
            const ulonglong2 q0 = sh[0], q1 = sh[1], q2 = sh[2], q3 = sh[3];
            const u64 hhp[8] = {q0.x, q0.y, q1.x, q1.y, q2.x, q2.y, q3.x, q3.y};
            const float h_prev = s_h[p][g][lane];
            if (active) out_h[((size_t)l * B_ + bb) * 16 + lane] = h_prev;

            u64 ar = pk2(bhr, 0.f), az = pk2(bhz, 0.f), an = pk2(bhn, 0.f);
#pragma unroll
            for (int k = 0; k < 8; k++) {
                ar = ffma2(vrp[k], hhp[k], ar);
                az = ffma2(vzp[k], hhp[k], az);
                an = ffma2(vnp[k], hhp[k], an);
            }
            float rl, rh, zl, zh, nl, nh;
            upk2(rl, rh, ar); upk2(zl, zh, az); upk2(nl, nh, an);
            const float r = sigf(cr[j] + (rl + rh));
            const float z = sigf(cz[j] + (zl + zh));
            const float n = mytanh(fmaf(r, nl + nh, cn[j]));
            const float h_new = fmaf(z, h_prev - n, n);
            s_h[1 - p][g][lane] = h_new;

            // decoder on hhp == h_all[l-1] → out_x[l-1]
            u64 aD0 = pk2(db1_0, 0.f), aD1 = pk2(db1_1, 0.f);
#pragma unroll
            for (int k = 0; k < 8; k++) {
                aD0 = ffma2(wd0[k], hhp[k], aD0);
                aD1 = ffma2(wd1[k], hhp[k], aD1);
            }
            float d0l, d0h, d1l, d1h;
            upk2(d0l, d0h, aD0); upk2(d1l, d1h, aD1);
            const float d0 = tanha(d0l + d0h);
            const float d1 = tanha(d1l + d1h);
            const u64 dpk = pk2(d0, d1);
            float pp0, pp1, pp2, pp3;
            { float lo, hi;
              upk2(lo, hi, fmul2(w2p[0], dpk)); pp0 = lo + hi;
              upk2(lo, hi, fmul2(w2p[1], dpk)); pp1 = lo + hi;
              upk2(lo, hi, fmul2(w2p[2], dpk)); pp2 = lo + hi;
              upk2(lo, hi, fmul2(w2p[3], dpk)); pp3 = lo + hi; }
            float q01  = (lane & 1) ? pp1 : pp0;
            float q01b = (lane & 1) ? pp0 : pp1;
            q01 += __shfl_xor_sync(0xffffffffu, q01b, 1);
            float q23  = (lane & 1) ? pp3 : pp2;
            float q23b = (lane & 1) ? pp2 : pp3;
            q23 += __shfl_xor_sync(0xffffffffu, q23b, 1);
            float qq  = (lane & 2) ? q23 : q01;
            float qqb = (lane & 2) ? q01 : q23;
            qq += __shfl_xor_sync(0xffffffffu, qqb, 2);
            qq += __shfl_xor_sync(0xffffffffu, qq, 4);
            qq += __shfl_xor_sync(0xffffffffu, qq, 8);
            if (l > 0 && active && lane < 4)
                out_x[((size_t)(l - 1) * B_ + bb) * 4 + lane] = qq + db2;

            __syncwarp();
        }
#pragma unroll
        for (int j = 0; j < 8; j++) { cr[j] = nr[j]; cz[j] = nz[j]; cn[j] = nn_[j]; }
    }

    // tail: decode final hidden (in s_h[0]) → out_x[L-1]
    {
        const ulonglong2* sh = (const ulonglong2*)s_h[0][g];
        const ulonglong2 q0 = sh[0], q1 = sh[1], q2 = sh[2], q3 = sh[3];
        const u64 hhp[8] = {q0.x, q0.y, q1.x, q1.y, q2.x, q2.y, q3.x, q3.y};
        u64 aD0 = pk2(db1_0, 0.f), aD1 = pk2(db1_1, 0.f);
#pragma unroll
        for (int k = 0; k < 8; k++) {
            aD0 = ffma2(wd0[k], hhp[k], aD0);
            aD1 = ffma2(wd1[k], hhp[k], aD1);
        }
        float d0l, d0h, d1l, d1h;
        upk2(d0l, d0h, aD0); upk2(d1l, d1h, aD1);
        const float d0 = tanha(d0l + d0h);
        const float d1 = tanha(d1l + d1h);
        const u64 dpk = pk2(d0, d1);
        float pp0, pp1, pp2, pp3;
        { float lo, hi;
          upk2(lo, hi, fmul2(w2p[0], dpk)); pp0 = lo + hi;
          upk2(lo, hi, fmul2(w2p[1], dpk)); pp1 = lo + hi;
          upk2(lo, hi, fmul2(w2p[2], dpk)); pp2 = lo + hi;
          upk2(lo, hi, fmul2(w2p[3], dpk)); pp3 = lo + hi; }
        float q01  = (lane & 1) ? pp1 : pp0;
        float q01b = (lane & 1) ? pp0 : pp1;
        q01 += __shfl_xor_sync(0xffffffffu, q01b, 1);
        float q23  = (lane & 1) ? pp3 : pp2;
        float q23b = (lane & 1) ? pp2 : pp3;
        q23 += __shfl_xor_sync(0xffffffffu, q23b, 1);
        float qq  = (lane & 2) ? q23 : q01;
        float qqb = (lane & 2) ? q01 : q23;
        qq += __shfl_xor_sync(0xffffffffu, qqb, 2);
        qq += __shfl_xor_sync(0xffffffffu, qq, 4);
        qq += __shfl_xor_sync(0xffffffffu, qq, 8);
        if (active && lane < 4)
            out_x[((size_t)(L_ - 1) * B_ + bb) * 4 + lane] = qq + db2;
    }
}

// ============================================================================
extern "C" void kernel_launch(void* const* d_in, const int* in_sizes, int n_in,
                              void* d_out, int out_size) {
    const float* u_in   = (const float*)d_in[0];
    const float* x_in   = (const float*)d_in[1];
    const float* pu_W1  = (const float*)d_in[2];
    const float* pu_b1  = (const float*)d_in[3];
    const float* pu_W2  = (const float*)d_in[4];
    const float* pu_b2  = (const float*)d_in[5];
    const float* px_W1  = (const float*)d_in[6];
    const float* px_b1  = (const float*)d_in[7];
    const float* px_W2  = (const float*)d_in[8];
    const float* px_b2  = (const float*)d_in[9];
    const float* W_ih   = (const float*)d_in[10];
    const float* b_ih   = (const float*)d_in[11];
    const float* W_hh   = (const float*)d_in[12];
    const float* b_hh   = (const float*)d_in[13];
    const float* dec_W1 = (const float*)d_in[14];
    const float* dec_b1 = (const float*)d_in[15];
    const float* dec_W2 = (const float*)d_in[16];
    const float* dec_b2 = (const float*)d_in[17];

    float* out_x = (float*)d_out;                          // [L,B,4]
    float* out_h = (float*)d_out + (size_t)L_ * B_ * 4;    // [L,B,16]

    k1_gates<<<NE / K1T, K1T>>>(u_in, x_in, pu_W1, pu_b1, pu_W2, pu_b2,
                                px_W1, px_b1, px_W2, px_b2, W_ih, b_ih);
    k2_recur<<<(B_ + BPC - 1) / BPC, NT2>>>(W_hh, b_hh,
                                            dec_W1, dec_b1, dec_W2, dec_b2,
                                            out_h, out_x);
}